// round 3
// baseline (speedup 1.0000x reference)
#include <cuda_runtime.h>

#define EMB   1024
#define CTXT  2048
#define MROWS 4096   // BATCH * CTXT
#define NH    16
#define HS    64

// Scratch (allocation-free rule: __device__ globals)
__device__ float g_Q[MROWS * EMB];
__device__ float g_K[MROWS * EMB];
__device__ float g_V[MROWS * EMB];
__device__ float g_AO[MROWS * EMB];

// ---------------------------------------------------------------------------
// 128x128 tile GEMM: C[128,128] = A[M,1024] * B[1024,1024] + bias
// 256 threads, 8x8 per thread (split 4+4 frags for conflict-free smem reads)
// ---------------------------------------------------------------------------
__device__ __forceinline__ void gemm_tile(const float* __restrict__ A,
                                          const float* __restrict__ B,
                                          const float* __restrict__ bias,
                                          float* __restrict__ C)
{
    __shared__ float As[16][132];   // transposed A tile, padded (store-conflict relief)
    __shared__ float Bs[16][128];

    const int tid = threadIdx.x;
    const int tx = tid & 15;
    const int ty = tid >> 4;
    const int row0 = blockIdx.y << 7;
    const int col0 = blockIdx.x << 7;

    float acc[8][8];
#pragma unroll
    for (int i = 0; i < 8; ++i)
#pragma unroll
        for (int j = 0; j < 8; ++j) acc[i][j] = 0.f;

    for (int k0 = 0; k0 < EMB; k0 += 16) {
#pragma unroll
        for (int u = 0; u < 2; ++u) {
            int id = tid + (u << 8);
            // A tile: 128 rows x 16 cols, store transposed
            int ar = id >> 2;
            int ac = (id & 3) << 2;
            float4 av = *(const float4*)(A + (size_t)(row0 + ar) * EMB + k0 + ac);
            As[ac + 0][ar] = av.x;
            As[ac + 1][ar] = av.y;
            As[ac + 2][ar] = av.z;
            As[ac + 3][ar] = av.w;
            // B tile: 16 rows x 128 cols
            int br = id >> 5;
            int bc = (id & 31) << 2;
            *(float4*)(&Bs[br][bc]) = *(const float4*)(B + (size_t)(k0 + br) * EMB + col0 + bc);
        }
        __syncthreads();
#pragma unroll
        for (int k = 0; k < 16; ++k) {
            float a[8], b[8];
            *(float4*)(a)     = *(const float4*)(&As[k][ty << 2]);
            *(float4*)(a + 4) = *(const float4*)(&As[k][64 + (ty << 2)]);
            *(float4*)(b)     = *(const float4*)(&Bs[k][tx << 2]);
            *(float4*)(b + 4) = *(const float4*)(&Bs[k][64 + (tx << 2)]);
#pragma unroll
            for (int i = 0; i < 8; ++i)
#pragma unroll
                for (int j = 0; j < 8; ++j)
                    acc[i][j] += a[i] * b[j];
        }
        __syncthreads();
    }

#pragma unroll
    for (int i = 0; i < 8; ++i) {
        int r = row0 + ((i < 4) ? (ty * 4 + i) : (64 + ty * 4 + (i - 4)));
#pragma unroll
        for (int jh = 0; jh < 2; ++jh) {
            int c = col0 + jh * 64 + tx * 4;
            float4 v;
            v.x = acc[i][jh * 4 + 0] + bias[c + 0];
            v.y = acc[i][jh * 4 + 1] + bias[c + 1];
            v.z = acc[i][jh * 4 + 2] + bias[c + 2];
            v.w = acc[i][jh * 4 + 3] + bias[c + 3];
            *(float4*)(C + (size_t)r * EMB + c) = v;
        }
    }
}

__global__ __launch_bounds__(256) void qkv_kernel(
    const float* __restrict__ x,
    const float* __restrict__ Wq, const float* __restrict__ bq,
    const float* __restrict__ Wk, const float* __restrict__ bk,
    const float* __restrict__ Wv, const float* __restrict__ bv)
{
    const float* W; const float* bias; float* C;
    if (blockIdx.z == 0)      { W = Wq; bias = bq; C = g_Q; }
    else if (blockIdx.z == 1) { W = Wk; bias = bk; C = g_K; }
    else                      { W = Wv; bias = bv; C = g_V; }
    gemm_tile(x, W, bias, C);
}

__global__ __launch_bounds__(256) void out_proj_kernel(
    const float* __restrict__ Wo, const float* __restrict__ bo,
    float* __restrict__ out)
{
    gemm_tile(g_AO, Wo, bo, out);
}

// ---------------------------------------------------------------------------
// Flash attention (causal, online softmax), fp32.
// Grid: (T/64, B*H). Block: 256 threads (16 tx x 16 ty), 4x4 frag -> 64x64 tile
// ---------------------------------------------------------------------------
#define FLASH_SMEM ((3 * 64 * 65 + 64 * 64) * 4)

__global__ __launch_bounds__(256) void flash_kernel()
{
    extern __shared__ float sm[];
    float* Qs = sm;                 // [64][65]
    float* Ks = sm + 64 * 65;       // [64][65]
    float* Ps = sm + 2 * 64 * 65;   // [64][65]
    float* Vs = sm + 3 * 64 * 65;   // [64][64] (16B-aligned: offset 49920B)

    const int tid = threadIdx.x;
    const int tx = tid & 15;
    const int ty = tid >> 4;
    const int b  = blockIdx.y >> 4;
    const int h  = blockIdx.y & 15;
    // longest q-blocks first (wave balance under causal work skew)
    const int q0 = (int)(gridDim.x - 1 - blockIdx.x) << 6;
    const size_t base = (size_t)b * CTXT;
    const int ch = h << 6;
    const float scale = 0.03125f;   // 1/sqrt(1024)

    // Load Q tile (pre-scaled)
    for (int i = tid; i < 64 * 16; i += 256) {
        int r = i >> 4, c = (i & 15) << 2;
        float4 v = *(const float4*)(&g_Q[(base + q0 + r) * EMB + ch + c]);
        Qs[r * 65 + c + 0] = v.x * scale;
        Qs[r * 65 + c + 1] = v.y * scale;
        Qs[r * 65 + c + 2] = v.z * scale;
        Qs[r * 65 + c + 3] = v.w * scale;
    }

    float o[4][4];
    float m[4], l[4];
#pragma unroll
    for (int i = 0; i < 4; ++i) {
        m[i] = -1e30f; l[i] = 0.f;
#pragma unroll
        for (int j = 0; j < 4; ++j) o[i][j] = 0.f;
    }

    for (int j0 = 0; j0 <= q0; j0 += 64) {
        // Load K,V tiles
        for (int i = tid; i < 64 * 16; i += 256) {
            int r = i >> 4, c = (i & 15) << 2;
            float4 kv = *(const float4*)(&g_K[(base + j0 + r) * EMB + ch + c]);
            Ks[r * 65 + c + 0] = kv.x;
            Ks[r * 65 + c + 1] = kv.y;
            Ks[r * 65 + c + 2] = kv.z;
            Ks[r * 65 + c + 3] = kv.w;
            *(float4*)(&Vs[r * 64 + c]) =
                *(const float4*)(&g_V[(base + j0 + r) * EMB + ch + c]);
        }
        __syncthreads();   // also covers the Qs stores on first iteration

        // S = Q * K^T  (4x4 frag per thread)
        float s[4][4];
#pragma unroll
        for (int i = 0; i < 4; ++i)
#pragma unroll
            for (int j = 0; j < 4; ++j) s[i][j] = 0.f;

#pragma unroll 4
        for (int d = 0; d < 64; ++d) {
            float q[4], k[4];
#pragma unroll
            for (int i = 0; i < 4; ++i) q[i] = Qs[(ty * 4 + i) * 65 + d];
#pragma unroll
            for (int j = 0; j < 4; ++j) k[j] = Ks[(tx * 4 + j) * 65 + d];
#pragma unroll
            for (int i = 0; i < 4; ++i)
#pragma unroll
                for (int j = 0; j < 4; ++j)
                    s[i][j] += q[i] * k[j];
        }

        // Causal mask on the diagonal block
        if (j0 == q0) {
#pragma unroll
            for (int i = 0; i < 4; ++i)
#pragma unroll
                for (int j = 0; j < 4; ++j)
                    if (tx * 4 + j > ty * 4 + i) s[i][j] = -1e30f;
        }

        // Online softmax (row reductions over the 16 tx lanes)
#pragma unroll
        for (int i = 0; i < 4; ++i) {
            float mx = fmaxf(fmaxf(s[i][0], s[i][1]), fmaxf(s[i][2], s[i][3]));
            mx = fmaxf(mx, __shfl_xor_sync(0xffffffffu, mx, 1));
            mx = fmaxf(mx, __shfl_xor_sync(0xffffffffu, mx, 2));
            mx = fmaxf(mx, __shfl_xor_sync(0xffffffffu, mx, 4));
            mx = fmaxf(mx, __shfl_xor_sync(0xffffffffu, mx, 8));
            float mn = fmaxf(m[i], mx);
            float alpha = __expf(m[i] - mn);
            m[i] = mn;
            float rs = 0.f;
#pragma unroll
            for (int j = 0; j < 4; ++j) {
                float p = __expf(s[i][j] - mn);
                Ps[(ty * 4 + i) * 65 + tx * 4 + j] = p;
                rs += p;
            }
            rs += __shfl_xor_sync(0xffffffffu, rs, 1);
            rs += __shfl_xor_sync(0xffffffffu, rs, 2);
            rs += __shfl_xor_sync(0xffffffffu, rs, 4);
            rs += __shfl_xor_sync(0xffffffffu, rs, 8);
            l[i] = l[i] * alpha + rs;
#pragma unroll
            for (int j = 0; j < 4; ++j) o[i][j] *= alpha;
        }
        __syncthreads();

        // O += P * V
#pragma unroll 4
        for (int jj = 0; jj < 64; ++jj) {
            float4 vv = *(const float4*)(&Vs[jj * 64 + tx * 4]);
#pragma unroll
            for (int i = 0; i < 4; ++i) {
                float p = Ps[(ty * 4 + i) * 65 + jj];
                o[i][0] += p * vv.x;
                o[i][1] += p * vv.y;
                o[i][2] += p * vv.z;
                o[i][3] += p * vv.w;
            }
        }
        __syncthreads();
    }

    // Epilogue: normalize, write [B,T,H*D] layout
#pragma unroll
    for (int i = 0; i < 4; ++i) {
        float inv = 1.f / l[i];
        float4 v;
        v.x = o[i][0] * inv;
        v.y = o[i][1] * inv;
        v.z = o[i][2] * inv;
        v.w = o[i][3] * inv;
        *(float4*)(&g_AO[(base + q0 + ty * 4 + i) * EMB + ch + tx * 4]) = v;
    }
}

// ---------------------------------------------------------------------------
extern "C" void kernel_launch(void* const* d_in, const int* in_sizes, int n_in,
                              void* d_out, int out_size)
{
    (void)in_sizes; (void)n_in; (void)out_size;
    const float* x  = (const float*)d_in[0];
    const float* Wk = (const float*)d_in[1];
    const float* bk = (const float*)d_in[2];
    const float* Wq = (const float*)d_in[3];
    const float* bq = (const float*)d_in[4];
    const float* Wv = (const float*)d_in[5];
    const float* bv = (const float*)d_in[6];
    const float* Wo = (const float*)d_in[7];
    const float* bo = (const float*)d_in[8];

    cudaFuncSetAttribute(flash_kernel,
                         cudaFuncAttributeMaxDynamicSharedMemorySize, FLASH_SMEM);

    qkv_kernel<<<dim3(8, 32, 3), 256>>>(x, Wq, bq, Wk, bk, Wv, bv);
    flash_kernel<<<dim3(32, 32), 256, FLASH_SMEM>>>();
    out_proj_kernel<<<dim3(8, 32), 256>>>(Wo, bo, (float*)d_out);
}

// round 5
// speedup vs baseline: 1.3383x; 1.3383x over previous
#include <cuda_runtime.h>
#include <cuda_bf16.h>
#include <cstdint>

#define EMB   1024
#define CTXT  2048
#define MROWS 4096   // BATCH * CTXT
#define NH    16
#define HS    64

// ---------------------------------------------------------------------------
// Device scratch (allocation-free rule)
// ---------------------------------------------------------------------------
__device__ float g_Q[MROWS * EMB];
__device__ float g_K[MROWS * EMB];
__device__ float g_V[MROWS * EMB];
__device__ float g_AO[MROWS * EMB];

__device__ __nv_bfloat16 g_xh[MROWS * EMB];
__device__ __nv_bfloat16 g_xl[MROWS * EMB];
__device__ __nv_bfloat16 g_aoh[MROWS * EMB];
__device__ __nv_bfloat16 g_aol[MROWS * EMB];
// transposed weights: slot 0=Wq, 1=Wk, 2=Wv, 3=Wo ; layout [n][k]
__device__ __nv_bfloat16 g_wth[4][EMB * EMB];
__device__ __nv_bfloat16 g_wtl[4][EMB * EMB];

// ---------------------------------------------------------------------------
__device__ __forceinline__ uint32_t smem_u32(const void* p) {
    uint32_t a;
    asm("{ .reg .u64 t; cvta.to.shared.u64 t, %1; cvt.u32.u64 %0, t; }"
        : "=r"(a) : "l"(p));
    return a;
}

#define MMA4(c, a, b0, b1)                                                   \
    asm volatile(                                                            \
        "mma.sync.aligned.m16n8k16.row.col.f32.bf16.bf16.f32 "               \
        "{%0,%1,%2,%3}, {%4,%5,%6,%7}, {%8,%9}, {%0,%1,%2,%3};"              \
        : "+f"((c)[0]), "+f"((c)[1]), "+f"((c)[2]), "+f"((c)[3])             \
        : "r"((a)[0]), "r"((a)[1]), "r"((a)[2]), "r"((a)[3]),                \
          "r"(b0), "r"(b1))

__device__ __forceinline__ uint32_t lds32(const __nv_bfloat16* p) {
    return *(const uint32_t*)p;
}

// ---------------------------------------------------------------------------
// Split kernels: fp32 -> bf16 hi/lo
// ---------------------------------------------------------------------------
__device__ __forceinline__ void split2(float v, __nv_bfloat16& h, __nv_bfloat16& l) {
    h = __float2bfloat16(v);
    l = __float2bfloat16(v - __bfloat162float(h));
}

__device__ __forceinline__ void split_body(const float* __restrict__ src,
                                           __nv_bfloat16* __restrict__ H,
                                           __nv_bfloat16* __restrict__ L) {
    int i = blockIdx.x * 256 + threadIdx.x;   // 4 elems per thread
    float4 v = *(const float4*)(src + (size_t)i * 4);
    __nv_bfloat16 h0, h1, h2, h3, l0, l1, l2, l3;
    split2(v.x, h0, l0); split2(v.y, h1, l1);
    split2(v.z, h2, l2); split2(v.w, h3, l3);
    __nv_bfloat162* H2 = (__nv_bfloat162*)H;
    __nv_bfloat162* L2 = (__nv_bfloat162*)L;
    H2[(size_t)i * 2 + 0] = __nv_bfloat162{h0, h1};
    H2[(size_t)i * 2 + 1] = __nv_bfloat162{h2, h3};
    L2[(size_t)i * 2 + 0] = __nv_bfloat162{l0, l1};
    L2[(size_t)i * 2 + 1] = __nv_bfloat162{l2, l3};
}

__global__ __launch_bounds__(256) void split_x_kernel(const float* __restrict__ x) {
    split_body(x, g_xh, g_xl);
}
__global__ __launch_bounds__(256) void split_ao_kernel() {
    split_body(g_AO, g_aoh, g_aol);
}

// Transpose + split weights: W[k][n] (row-major) -> WT[n][k] bf16 hi/lo
__global__ __launch_bounds__(256) void split_wt_kernel(
    const float* __restrict__ Wq, const float* __restrict__ Wk,
    const float* __restrict__ Wv, const float* __restrict__ Wo)
{
    __shared__ float ts[32][33];
    const int z = blockIdx.z;
    const float* W = (z == 0) ? Wq : (z == 1) ? Wk : (z == 2) ? Wv : Wo;
    const int row0 = blockIdx.y << 5;   // k
    const int col0 = blockIdx.x << 5;   // n
    const int c = threadIdx.x & 31, r8 = threadIdx.x >> 5;
#pragma unroll
    for (int it = 0; it < 4; ++it) {
        int r = it * 8 + r8;
        ts[r][c] = W[(size_t)(row0 + r) * EMB + col0 + c];
    }
    __syncthreads();
#pragma unroll
    for (int it = 0; it < 4; ++it) {
        int r = it * 8 + r8;
        float v = ts[c][r];   // = W[row0+c][col0+r]
        __nv_bfloat16 h, l; split2(v, h, l);
        size_t o = (size_t)(col0 + r) * EMB + row0 + c;
        g_wth[z][o] = h;
        g_wtl[z][o] = l;
    }
}

// ---------------------------------------------------------------------------
// bf16x3 GEMM via mma.sync (HMMA): C[128,128] tile, K=1024, fp32 accum.
// 8 warps (4M x 2N), warp tile 32x64. K chunks of 32, cp.async double buffer.
// smem per stage: Ah/Al/Bh/Bl each [128][40] bf16 (40-half padded stride).
// ---------------------------------------------------------------------------
#define BK 32
#define ROWH 40                       // padded halves per row
#define MAT_HALVES (128 * ROWH)       // 5120
#define STAGE_HALVES (4 * MAT_HALVES) // 20480
#define STAGE_BYTES (STAGE_HALVES * 2)
#define MMA_SMEM (2 * STAGE_BYTES)    // 81920

__device__ void mma_gemm_body(const __nv_bfloat16* __restrict__ Ah,
                              const __nv_bfloat16* __restrict__ Al,
                              const __nv_bfloat16* __restrict__ Bh,
                              const __nv_bfloat16* __restrict__ Bl,
                              const float* __restrict__ bias,
                              float* __restrict__ C,
                              int row0, int col0)
{
    extern __shared__ __nv_bfloat16 sh[];
    const uint32_t sb = smem_u32(sh);

    const int tid  = threadIdx.x;
    const int lane = tid & 31;
    const int wid  = tid >> 5;
    const int g    = lane >> 2;       // groupID
    const int t4   = lane & 3;
    const int wm   = wid & 3;         // warp row (x32)
    const int wn   = wid >> 2;        // warp col (x64)

    float acc[2][8][4];
#pragma unroll
    for (int i = 0; i < 2; ++i)
#pragma unroll
        for (int j = 0; j < 8; ++j)
#pragma unroll
            for (int q = 0; q < 4; ++q) acc[i][j][q] = 0.f;

    const __nv_bfloat16* srcs[4] = {Ah, Al, Bh, Bl};

    // issue one K-chunk into stage s
    auto issue = [&](int kc, int s) {
        const uint32_t sbase = sb + s * STAGE_BYTES;
#pragma unroll
        for (int m = 0; m < 4; ++m) {
            const __nv_bfloat16* src = srcs[m];
            const int gb = (m < 2) ? row0 : col0;
#pragma unroll
            for (int h = 0; h < 2; ++h) {
                const int id = h * 256 + tid;       // 0..511
                const int r  = id >> 2;             // 0..127
                const int c4 = id & 3;              // 16B chunk
                const void* gp = src + (size_t)(gb + r) * EMB + kc + c4 * 8;
                const uint32_t sp = sbase + (m * MAT_HALVES + r * ROWH) * 2 + c4 * 16;
                asm volatile("cp.async.cg.shared.global [%0], [%1], 16;"
                             :: "r"(sp), "l"(gp));
            }
        }
        asm volatile("cp.async.commit_group;");
    };

    issue(0, 0);

    for (int c = 0; c < EMB / BK; ++c) {
        if (c + 1 < EMB / BK) {
            issue((c + 1) * BK, (c + 1) & 1);
            asm volatile("cp.async.wait_group 1;");
        } else {
            asm volatile("cp.async.wait_group 0;");
        }
        __syncthreads();

        const __nv_bfloat16* st = sh + (c & 1) * STAGE_HALVES;
        const __nv_bfloat16* stA = st;
        const __nv_bfloat16* stB = st + 2 * MAT_HALVES;

#pragma unroll
        for (int ks = 0; ks < 2; ++ks) {
            const int k = ks * 16 + t4 * 2;
            uint32_t ah[2][4], al[2][4];
#pragma unroll
            for (int ma = 0; ma < 2; ++ma) {
                const __nv_bfloat16* pa = stA + (wm * 32 + ma * 16 + g) * ROWH + k;
                ah[ma][0] = lds32(pa);
                ah[ma][1] = lds32(pa + 8 * ROWH);
                ah[ma][2] = lds32(pa + 8);
                ah[ma][3] = lds32(pa + 8 * ROWH + 8);
                const __nv_bfloat16* pl = pa + MAT_HALVES;
                al[ma][0] = lds32(pl);
                al[ma][1] = lds32(pl + 8 * ROWH);
                al[ma][2] = lds32(pl + 8);
                al[ma][3] = lds32(pl + 8 * ROWH + 8);
            }
#pragma unroll
            for (int na = 0; na < 8; ++na) {
                const __nv_bfloat16* pb = stB + (wn * 64 + na * 8 + g) * ROWH + k;
                uint32_t bh0 = lds32(pb);
                uint32_t bh1 = lds32(pb + 8);
                uint32_t bl0 = lds32(pb + MAT_HALVES);
                uint32_t bl1 = lds32(pb + MAT_HALVES + 8);
#pragma unroll
                for (int ma = 0; ma < 2; ++ma) {
                    MMA4(acc[ma][na], ah[ma], bh0, bh1);
                    MMA4(acc[ma][na], ah[ma], bl0, bl1);
                    MMA4(acc[ma][na], al[ma], bh0, bh1);
                }
            }
        }
        __syncthreads();
    }

    // Epilogue
#pragma unroll
    for (int na = 0; na < 8; ++na) {
        const int n = col0 + wn * 64 + na * 8 + t4 * 2;
        const float bz0 = bias[n], bz1 = bias[n + 1];
#pragma unroll
        for (int ma = 0; ma < 2; ++ma) {
            const int mr = row0 + wm * 32 + ma * 16 + g;
            float2 v0 = {acc[ma][na][0] + bz0, acc[ma][na][1] + bz1};
            float2 v1 = {acc[ma][na][2] + bz0, acc[ma][na][3] + bz1};
            *(float2*)(C + (size_t)mr * EMB + n) = v0;
            *(float2*)(C + (size_t)(mr + 8) * EMB + n) = v1;
        }
    }
}

__global__ __launch_bounds__(256, 1) void mma_qkv_kernel(
    const float* __restrict__ bq, const float* __restrict__ bk,
    const float* __restrict__ bv)
{
    const int z = blockIdx.z;
    const float* bias = (z == 0) ? bq : (z == 1) ? bk : bv;
    float* C = (z == 0) ? g_Q : (z == 1) ? g_K : g_V;
    mma_gemm_body(g_xh, g_xl, g_wth[z], g_wtl[z], bias, C,
                  blockIdx.y << 7, blockIdx.x << 7);
}

__global__ __launch_bounds__(256, 1) void mma_out_kernel(
    const float* __restrict__ bo, float* __restrict__ out)
{
    mma_gemm_body(g_aoh, g_aol, g_wth[3], g_wtl[3], bo, out,
                  blockIdx.y << 7, blockIdx.x << 7);
}

// ---------------------------------------------------------------------------
// Flash attention (causal, online softmax), fp32.
// Q,K staged d-major transposed -> 2x LDS.128 per 16 FFMA in QK^T loop.
// Grid: (T/64, B*H). Block: 256 threads (16 tx x 16 ty), 4x4 frag.
// ---------------------------------------------------------------------------
#define FLASH_SMEM ((2 * 64 * 68 + 64 * 65 + 64 * 64) * 4)

__global__ __launch_bounds__(256) void flash_kernel()
{
    extern __shared__ float sm[];
    float* Qt = sm;                         // [64 d][68]
    float* Kt = sm + 64 * 68;               // [64 d][68]
    float* Ps = sm + 2 * 64 * 68;           // [64][65]
    float* Vs = sm + 2 * 64 * 68 + 64 * 65; // [64][64]

    const int tid = threadIdx.x;
    const int tx = tid & 15;
    const int ty = tid >> 4;
    const int b  = blockIdx.y >> 4;
    const int h  = blockIdx.y & 15;
    const int q0 = (int)(gridDim.x - 1 - blockIdx.x) << 6;  // longest first
    const size_t base = (size_t)b * CTXT;
    const int ch = h << 6;
    const float scale = 0.03125f;   // 1/sqrt(1024)

    for (int i = tid; i < 64 * 16; i += 256) {
        int r = i >> 4, c = (i & 15) << 2;
        float4 v = *(const float4*)(&g_Q[(base + q0 + r) * EMB + ch + c]);
        Qt[(c + 0) * 68 + r] = v.x * scale;
        Qt[(c + 1) * 68 + r] = v.y * scale;
        Qt[(c + 2) * 68 + r] = v.z * scale;
        Qt[(c + 3) * 68 + r] = v.w * scale;
    }

    float o[4][4];
    float m[4], l[4];
#pragma unroll
    for (int i = 0; i < 4; ++i) {
        m[i] = -1e30f; l[i] = 0.f;
#pragma unroll
        for (int j = 0; j < 4; ++j) o[i][j] = 0.f;
    }

    for (int j0 = 0; j0 <= q0; j0 += 64) {
        for (int i = tid; i < 64 * 16; i += 256) {
            int r = i >> 4, c = (i & 15) << 2;
            float4 kv = *(const float4*)(&g_K[(base + j0 + r) * EMB + ch + c]);
            Kt[(c + 0) * 68 + r] = kv.x;
            Kt[(c + 1) * 68 + r] = kv.y;
            Kt[(c + 2) * 68 + r] = kv.z;
            Kt[(c + 3) * 68 + r] = kv.w;
            *(float4*)(&Vs[r * 64 + c]) =
                *(const float4*)(&g_V[(base + j0 + r) * EMB + ch + c]);
        }
        __syncthreads();

        float s[4][4];
#pragma unroll
        for (int i = 0; i < 4; ++i)
#pragma unroll
            for (int j = 0; j < 4; ++j) s[i][j] = 0.f;

#pragma unroll 4
        for (int d = 0; d < 64; ++d) {
            float4 q = *(const float4*)(&Qt[d * 68 + (ty << 2)]);
            float4 k = *(const float4*)(&Kt[d * 68 + (tx << 2)]);
            s[0][0] += q.x * k.x; s[0][1] += q.x * k.y; s[0][2] += q.x * k.z; s[0][3] += q.x * k.w;
            s[1][0] += q.y * k.x; s[1][1] += q.y * k.y; s[1][2] += q.y * k.z; s[1][3] += q.y * k.w;
            s[2][0] += q.z * k.x; s[2][1] += q.z * k.y; s[2][2] += q.z * k.z; s[2][3] += q.z * k.w;
            s[3][0] += q.w * k.x; s[3][1] += q.w * k.y; s[3][2] += q.w * k.z; s[3][3] += q.w * k.w;
        }

        if (j0 == q0) {
#pragma unroll
            for (int i = 0; i < 4; ++i)
#pragma unroll
                for (int j = 0; j < 4; ++j)
                    if (tx * 4 + j > ty * 4 + i) s[i][j] = -1e30f;
        }

#pragma unroll
        for (int i = 0; i < 4; ++i) {
            float mx = fmaxf(fmaxf(s[i][0], s[i][1]), fmaxf(s[i][2], s[i][3]));
            mx = fmaxf(mx, __shfl_xor_sync(0xffffffffu, mx, 1));
            mx = fmaxf(mx, __shfl_xor_sync(0xffffffffu, mx, 2));
            mx = fmaxf(mx, __shfl_xor_sync(0xffffffffu, mx, 4));
            mx = fmaxf(mx, __shfl_xor_sync(0xffffffffu, mx, 8));
            float mn = fmaxf(m[i], mx);
            float alpha = __expf(m[i] - mn);
            m[i] = mn;
            float rs = 0.f;
#pragma unroll
            for (int j = 0; j < 4; ++j) {
                float p = __expf(s[i][j] - mn);
                Ps[(ty * 4 + i) * 65 + tx * 4 + j] = p;
                rs += p;
            }
            rs += __shfl_xor_sync(0xffffffffu, rs, 1);
            rs += __shfl_xor_sync(0xffffffffu, rs, 2);
            rs += __shfl_xor_sync(0xffffffffu, rs, 4);
            rs += __shfl_xor_sync(0xffffffffu, rs, 8);
            l[i] = l[i] * alpha + rs;
#pragma unroll
            for (int j = 0; j < 4; ++j) o[i][j] *= alpha;
        }
        __syncthreads();

#pragma unroll 4
        for (int jj = 0; jj < 64; ++jj) {
            float4 vv = *(const float4*)(&Vs[jj * 64 + tx * 4]);
#pragma unroll
            for (int i = 0; i < 4; ++i) {
                float p = Ps[(ty * 4 + i) * 65 + jj];
                o[i][0] += p * vv.x;
                o[i][1] += p * vv.y;
                o[i][2] += p * vv.z;
                o[i][3] += p * vv.w;
            }
        }
        __syncthreads();
    }

#pragma unroll
    for (int i = 0; i < 4; ++i) {
        float inv = 1.f / l[i];
        float4 v;
        v.x = o[i][0] * inv;
        v.y = o[i][1] * inv;
        v.z = o[i][2] * inv;
        v.w = o[i][3] * inv;
        *(float4*)(&g_AO[(base + q0 + ty * 4 + i) * EMB + ch + tx * 4]) = v;
    }
}

// ---------------------------------------------------------------------------
extern "C" void kernel_launch(void* const* d_in, const int* in_sizes, int n_in,
                              void* d_out, int out_size)
{
    (void)in_sizes; (void)n_in; (void)out_size;
    const float* x  = (const float*)d_in[0];
    const float* Wk = (const float*)d_in[1];
    const float* bk = (const float*)d_in[2];
    const float* Wq = (const float*)d_in[3];
    const float* bq = (const float*)d_in[4];
    const float* Wv = (const float*)d_in[5];
    const float* bv = (const float*)d_in[6];
    const float* Wo = (const float*)d_in[7];
    const float* bo = (const float*)d_in[8];

    cudaFuncSetAttribute(flash_kernel,
                         cudaFuncAttributeMaxDynamicSharedMemorySize, FLASH_SMEM);
    cudaFuncSetAttribute(mma_qkv_kernel,
                         cudaFuncAttributeMaxDynamicSharedMemorySize, MMA_SMEM);
    cudaFuncSetAttribute(mma_out_kernel,
                         cudaFuncAttributeMaxDynamicSharedMemorySize, MMA_SMEM);

    split_x_kernel<<<4096, 256>>>(x);
    split_wt_kernel<<<dim3(32, 32, 4), 256>>>(Wq, Wk, Wv, Wo);
    mma_qkv_kernel<<<dim3(8, 32, 3), 256, MMA_SMEM>>>(bq, bk, bv);
    flash_kernel<<<dim3(32, 32), 256, FLASH_SMEM>>>();
    split_ao_kernel<<<4096, 256>>>();
    mma_out_kernel<<<dim3(8, 32), 256, MMA_SMEM>>>(bo, (float*)d_out);
}

// round 6
// speedup vs baseline: 2.3248x; 1.7371x over previous
#include <cuda_runtime.h>
#include <cuda_bf16.h>
#include <cstdint>

#define EMB   1024
#define CTXT  2048
#define MROWS 4096   // BATCH * CTXT
#define NH    16
#define HS    64

// ---------------------------------------------------------------------------
// Device scratch (allocation-free rule)
// ---------------------------------------------------------------------------
__device__ float g_V[MROWS * EMB];

__device__ __nv_bfloat16 g_xh[MROWS * EMB];
__device__ __nv_bfloat16 g_xl[MROWS * EMB];
__device__ __nv_bfloat16 g_Qh[MROWS * EMB];   // pre-scaled by 1/32
__device__ __nv_bfloat16 g_Ql[MROWS * EMB];
__device__ __nv_bfloat16 g_Kh[MROWS * EMB];
__device__ __nv_bfloat16 g_Kl[MROWS * EMB];
__device__ __nv_bfloat16 g_Vth[MROWS * EMB];  // [b][h][d][j]
__device__ __nv_bfloat16 g_Vtl[MROWS * EMB];
__device__ __nv_bfloat16 g_aoh[MROWS * EMB];
__device__ __nv_bfloat16 g_aol[MROWS * EMB];
// transposed weights: slot 0=Wq, 1=Wk, 2=Wv, 3=Wo ; layout [n][k]
__device__ __nv_bfloat16 g_wth[4][EMB * EMB];
__device__ __nv_bfloat16 g_wtl[4][EMB * EMB];

// ---------------------------------------------------------------------------
__device__ __forceinline__ uint32_t smem_u32(const void* p) {
    uint32_t a;
    asm("{ .reg .u64 t; cvta.to.shared.u64 t, %1; cvt.u32.u64 %0, t; }"
        : "=r"(a) : "l"(p));
    return a;
}

#define MMA4(c, a, b0, b1)                                                   \
    asm volatile(                                                            \
        "mma.sync.aligned.m16n8k16.row.col.f32.bf16.bf16.f32 "               \
        "{%0,%1,%2,%3}, {%4,%5,%6,%7}, {%8,%9}, {%0,%1,%2,%3};"              \
        : "+f"((c)[0]), "+f"((c)[1]), "+f"((c)[2]), "+f"((c)[3])             \
        : "r"((a)[0]), "r"((a)[1]), "r"((a)[2]), "r"((a)[3]),                \
          "r"(b0), "r"(b1))

__device__ __forceinline__ uint32_t lds32(const __nv_bfloat16* p) {
    return *(const uint32_t*)p;
}
__device__ __forceinline__ uint32_t ldsu(uint32_t a) {
    uint32_t v;
    asm volatile("ld.shared.b32 %0, [%1];" : "=r"(v) : "r"(a));
    return v;
}
__device__ __forceinline__ void cpa16(uint32_t s, const void* g) {
    asm volatile("cp.async.cg.shared.global [%0], [%1], 16;" :: "r"(s), "l"(g));
}

__device__ __forceinline__ void split2(float v, __nv_bfloat16& h, __nv_bfloat16& l) {
    h = __float2bfloat16(v);
    l = __float2bfloat16(v - __bfloat162float(h));
}
// split pair (x,y) -> packed bf16x2 hi + lo
__device__ __forceinline__ void splitpair(float x, float y, uint32_t& hi, uint32_t& lo) {
    __nv_bfloat16 hx, lx, hy, ly;
    split2(x, hx, lx);
    split2(y, hy, ly);
    __nv_bfloat162 hp{hx, hy}, lp{lx, ly};
    hi = *(uint32_t*)&hp;
    lo = *(uint32_t*)&lp;
}

// ---------------------------------------------------------------------------
// Split x: fp32 -> bf16 hi/lo
// ---------------------------------------------------------------------------
__global__ __launch_bounds__(256) void split_x_kernel(const float* __restrict__ x) {
    int i = blockIdx.x * 256 + threadIdx.x;
    float4 v = *(const float4*)(x + (size_t)i * 4);
    uint32_t h0, l0, h1, l1;
    splitpair(v.x, v.y, h0, l0);
    splitpair(v.z, v.w, h1, l1);
    uint32_t* H = (uint32_t*)g_xh;
    uint32_t* L = (uint32_t*)g_xl;
    H[(size_t)i * 2 + 0] = h0;
    H[(size_t)i * 2 + 1] = h1;
    L[(size_t)i * 2 + 0] = l0;
    L[(size_t)i * 2 + 1] = l1;
}

// Transpose + split weights: W[k][n] -> WT[n][k] bf16 hi/lo
__global__ __launch_bounds__(256) void split_wt_kernel(
    const float* __restrict__ Wq, const float* __restrict__ Wk,
    const float* __restrict__ Wv, const float* __restrict__ Wo)
{
    __shared__ float ts[32][33];
    const int z = blockIdx.z;
    const float* W = (z == 0) ? Wq : (z == 1) ? Wk : (z == 2) ? Wv : Wo;
    const int row0 = blockIdx.y << 5;   // k
    const int col0 = blockIdx.x << 5;   // n
    const int c = threadIdx.x & 31, r8 = threadIdx.x >> 5;
#pragma unroll
    for (int it = 0; it < 4; ++it) {
        int r = it * 8 + r8;
        ts[r][c] = W[(size_t)(row0 + r) * EMB + col0 + c];
    }
    __syncthreads();
#pragma unroll
    for (int it = 0; it < 4; ++it) {
        int r = it * 8 + r8;
        float v = ts[c][r];
        __nv_bfloat16 h, l; split2(v, h, l);
        size_t o = (size_t)(col0 + r) * EMB + row0 + c;
        g_wth[z][o] = h;
        g_wtl[z][o] = l;
    }
}

// V -> transposed d-major bf16 hi/lo: g_Vth[(bh*64+d)*CTXT + j]
__global__ __launch_bounds__(256) void v_split_t_kernel() {
    __shared__ float ts[32][65];
    const int tid = threadIdx.x;
    const int bh = blockIdx.y, b = bh >> 4, h = bh & 15;
    const int j0 = blockIdx.x << 5;
    {
        int j = tid >> 3, dc = (tid & 7) << 3;
        const float* src = g_V + (size_t)(b * CTXT + j0 + j) * EMB + h * 64 + dc;
        float4 v0 = *(const float4*)src;
        float4 v1 = *(const float4*)(src + 4);
        ts[j][dc + 0] = v0.x; ts[j][dc + 1] = v0.y;
        ts[j][dc + 2] = v0.z; ts[j][dc + 3] = v0.w;
        ts[j][dc + 4] = v1.x; ts[j][dc + 5] = v1.y;
        ts[j][dc + 6] = v1.z; ts[j][dc + 7] = v1.w;
    }
    __syncthreads();
    {
        int d = tid >> 2, jq = (tid & 3) << 3;
        uint32_t hb[4], lb[4];
#pragma unroll
        for (int i = 0; i < 4; ++i)
            splitpair(ts[jq + 2 * i][d], ts[jq + 2 * i + 1][d], hb[i], lb[i]);
        size_t off = ((size_t)bh * 64 + d) * CTXT + j0 + jq;
        *(uint4*)(g_Vth + off) = *(uint4*)hb;
        *(uint4*)(g_Vtl + off) = *(uint4*)lb;
    }
}

// ---------------------------------------------------------------------------
// bf16x3 GEMM via mma.sync: C[128,128] tile, K=1024, fp32 accum.
// 8 warps (4M x 2N). K chunks of 32, cp.async double buffer.
// Epilogue: fp32 out (Cf) OR scaled bf16 hi/lo out (Ch/Cl).
// ---------------------------------------------------------------------------
#define BK 32
#define ROWH 40
#define MAT_HALVES (128 * ROWH)
#define STAGE_HALVES (4 * MAT_HALVES)
#define STAGE_BYTES (STAGE_HALVES * 2)
#define MMA_SMEM (2 * STAGE_BYTES)

__device__ void mma_gemm_body(const __nv_bfloat16* __restrict__ Ah,
                              const __nv_bfloat16* __restrict__ Al,
                              const __nv_bfloat16* __restrict__ Bh,
                              const __nv_bfloat16* __restrict__ Bl,
                              const float* __restrict__ bias,
                              float* __restrict__ Cf,
                              __nv_bfloat16* __restrict__ Ch,
                              __nv_bfloat16* __restrict__ Cl,
                              float scale,
                              int row0, int col0)
{
    extern __shared__ __nv_bfloat16 sh[];
    const uint32_t sb = smem_u32(sh);

    const int tid  = threadIdx.x;
    const int lane = tid & 31;
    const int wid  = tid >> 5;
    const int g    = lane >> 2;
    const int t4   = lane & 3;
    const int wm   = wid & 3;
    const int wn   = wid >> 2;

    float acc[2][8][4];
#pragma unroll
    for (int i = 0; i < 2; ++i)
#pragma unroll
        for (int j = 0; j < 8; ++j)
#pragma unroll
            for (int q = 0; q < 4; ++q) acc[i][j][q] = 0.f;

    const __nv_bfloat16* srcs[4] = {Ah, Al, Bh, Bl};

    auto issue = [&](int kc, int s) {
        const uint32_t sbase = sb + s * STAGE_BYTES;
#pragma unroll
        for (int m = 0; m < 4; ++m) {
            const __nv_bfloat16* src = srcs[m];
            const int gb = (m < 2) ? row0 : col0;
#pragma unroll
            for (int h = 0; h < 2; ++h) {
                const int id = h * 256 + tid;
                const int r  = id >> 2;
                const int c4 = id & 3;
                const void* gp = src + (size_t)(gb + r) * EMB + kc + c4 * 8;
                cpa16(sbase + (m * MAT_HALVES + r * ROWH) * 2 + c4 * 16, gp);
            }
        }
        asm volatile("cp.async.commit_group;");
    };

    issue(0, 0);

    for (int c = 0; c < EMB / BK; ++c) {
        if (c + 1 < EMB / BK) {
            issue((c + 1) * BK, (c + 1) & 1);
            asm volatile("cp.async.wait_group 1;");
        } else {
            asm volatile("cp.async.wait_group 0;");
        }
        __syncthreads();

        const __nv_bfloat16* st = sh + (c & 1) * STAGE_HALVES;
        const __nv_bfloat16* stA = st;
        const __nv_bfloat16* stB = st + 2 * MAT_HALVES;

#pragma unroll
        for (int ks = 0; ks < 2; ++ks) {
            const int k = ks * 16 + t4 * 2;
            uint32_t ah[2][4], al[2][4];
#pragma unroll
            for (int ma = 0; ma < 2; ++ma) {
                const __nv_bfloat16* pa = stA + (wm * 32 + ma * 16 + g) * ROWH + k;
                ah[ma][0] = lds32(pa);
                ah[ma][1] = lds32(pa + 8 * ROWH);
                ah[ma][2] = lds32(pa + 8);
                ah[ma][3] = lds32(pa + 8 * ROWH + 8);
                const __nv_bfloat16* pl = pa + MAT_HALVES;
                al[ma][0] = lds32(pl);
                al[ma][1] = lds32(pl + 8 * ROWH);
                al[ma][2] = lds32(pl + 8);
                al[ma][3] = lds32(pl + 8 * ROWH + 8);
            }
#pragma unroll
            for (int na = 0; na < 8; ++na) {
                const __nv_bfloat16* pb = stB + (wn * 64 + na * 8 + g) * ROWH + k;
                uint32_t bh0 = lds32(pb);
                uint32_t bh1 = lds32(pb + 8);
                uint32_t bl0 = lds32(pb + MAT_HALVES);
                uint32_t bl1 = lds32(pb + MAT_HALVES + 8);
#pragma unroll
                for (int ma = 0; ma < 2; ++ma) {
                    MMA4(acc[ma][na], ah[ma], bh0, bh1);
                    MMA4(acc[ma][na], ah[ma], bl0, bl1);
                    MMA4(acc[ma][na], al[ma], bh0, bh1);
                }
            }
        }
        __syncthreads();
    }

#pragma unroll
    for (int na = 0; na < 8; ++na) {
        const int n = col0 + wn * 64 + na * 8 + t4 * 2;
        const float bz0 = bias[n], bz1 = bias[n + 1];
#pragma unroll
        for (int ma = 0; ma < 2; ++ma) {
            const int mr = row0 + wm * 32 + ma * 16 + g;
            float p0 = acc[ma][na][0] + bz0, p1 = acc[ma][na][1] + bz1;
            float p2 = acc[ma][na][2] + bz0, p3 = acc[ma][na][3] + bz1;
            if (Ch) {
                uint32_t h01, l01, h23, l23;
                splitpair(p0 * scale, p1 * scale, h01, l01);
                splitpair(p2 * scale, p3 * scale, h23, l23);
                *(uint32_t*)(Ch + (size_t)mr * EMB + n) = h01;
                *(uint32_t*)(Cl + (size_t)mr * EMB + n) = l01;
                *(uint32_t*)(Ch + (size_t)(mr + 8) * EMB + n) = h23;
                *(uint32_t*)(Cl + (size_t)(mr + 8) * EMB + n) = l23;
            } else {
                *(float2*)(Cf + (size_t)mr * EMB + n) = float2{p0, p1};
                *(float2*)(Cf + (size_t)(mr + 8) * EMB + n) = float2{p2, p3};
            }
        }
    }
}

__global__ __launch_bounds__(256, 1) void mma_qkv_kernel(
    const float* __restrict__ bq, const float* __restrict__ bk,
    const float* __restrict__ bv)
{
    const int z = blockIdx.z;
    const int r0 = blockIdx.y << 7, c0 = blockIdx.x << 7;
    if (z == 0)
        mma_gemm_body(g_xh, g_xl, g_wth[0], g_wtl[0], bq, nullptr,
                      g_Qh, g_Ql, 0.03125f, r0, c0);   // 1/sqrt(1024) folded
    else if (z == 1)
        mma_gemm_body(g_xh, g_xl, g_wth[1], g_wtl[1], bk, nullptr,
                      g_Kh, g_Kl, 1.0f, r0, c0);
    else
        mma_gemm_body(g_xh, g_xl, g_wth[2], g_wtl[2], bv, g_V,
                      nullptr, nullptr, 1.0f, r0, c0);
}

__global__ __launch_bounds__(256, 1) void mma_out_kernel(
    const float* __restrict__ bo, float* __restrict__ out)
{
    mma_gemm_body(g_aoh, g_aol, g_wth[3], g_wtl[3], bo, out,
                  nullptr, nullptr, 1.0f, blockIdx.y << 7, blockIdx.x << 7);
}

// ---------------------------------------------------------------------------
// Tensor-core flash attention (causal, online softmax), bf16x3.
// BM=128 (8 warps x 16 rows), BN=64. Grid: (T/128, B*H).
// smem (bytes): Qh[0] Ql[18432]; stages at 36864 + s*36864:
//   {Kh 0, Kl 9216, Vth 18432, Vtl 27648}; row stride 144 B.
// ---------------------------------------------------------------------------
#define QHB 0
#define QLB 18432
#define STG0 36864
#define STGSZ 36864
#define FLASH_SMEM (STG0 + 2 * STGSZ)   // 110592

__global__ __launch_bounds__(256) void flash_mma_kernel()
{
    extern __shared__ char fsm[];
    const uint32_t sb = smem_u32(fsm);
    const int tid = threadIdx.x;
    const int lane = tid & 31, wid = tid >> 5;
    const int g = lane >> 2, t4 = lane & 3;
    const int bh = blockIdx.y, b = bh >> 4, h = bh & 15;
    const int qb = (int)(gridDim.x - 1 - blockIdx.x);   // longest first
    const int q0 = qb << 7;
    const size_t base = (size_t)b * CTXT;
    const int ch = h << 6;
    const int rbase = q0 + wid * 16;

    // Q tile hi/lo: 128 rows x 128 B each
    for (int i = tid; i < 1024; i += 256) {
        const int r = i >> 3, c4 = i & 7;
        const size_t go = (base + q0 + r) * EMB + ch + c4 * 8;
        cpa16(sb + QHB + r * 144 + c4 * 16, g_Qh + go);
        cpa16(sb + QLB + r * 144 + c4 * 16, g_Ql + go);
    }

    auto issue_kv = [&](int j0, int s) {
        const uint32_t kb = sb + STG0 + s * STGSZ;
        for (int i = tid; i < 512; i += 256) {
            const int r = i >> 3, c4 = i & 7;
            const uint32_t so = r * 144 + c4 * 16;
            const size_t ko = (base + j0 + r) * EMB + ch + c4 * 8;
            cpa16(kb + so, g_Kh + ko);
            cpa16(kb + 9216 + so, g_Kl + ko);
            const size_t vo = ((size_t)bh * 64 + r) * CTXT + j0 + c4 * 8;
            cpa16(kb + 18432 + so, g_Vth + vo);
            cpa16(kb + 27648 + so, g_Vtl + vo);
        }
    };

    issue_kv(0, 0);
    asm volatile("cp.async.commit_group;");

    float o[8][4];
#pragma unroll
    for (int nt = 0; nt < 8; ++nt)
#pragma unroll
        for (int q = 0; q < 4; ++q) o[nt][q] = 0.f;
    float m0 = -1e30f, m1 = -1e30f, l0 = 0.f, l1 = 0.f;

    const int nblocks = qb * 2 + 2;
    for (int jb = 0; jb < nblocks; ++jb) {
        const int j0 = jb << 6;
        if (jb + 1 < nblocks) {
            issue_kv((jb + 1) << 6, (jb + 1) & 1);
            asm volatile("cp.async.commit_group;");
            asm volatile("cp.async.wait_group 1;");
        } else {
            asm volatile("cp.async.wait_group 0;");
        }
        __syncthreads();

        if (j0 <= rbase + 15) {   // not fully masked for this warp
            const uint32_t kb = sb + STG0 + (jb & 1) * STGSZ;

            // ---- S = Q K^T (bf16x3) ----
            float sc[8][4];
#pragma unroll
            for (int nt = 0; nt < 8; ++nt)
#pragma unroll
                for (int q = 0; q < 4; ++q) sc[nt][q] = 0.f;

#pragma unroll
            for (int kk = 0; kk < 4; ++kk) {
                const uint32_t qa = sb + (wid * 16 + g) * 144 + kk * 32 + t4 * 4;
                uint32_t ah[4], al[4];
                ah[0] = ldsu(qa);
                ah[1] = ldsu(qa + 8 * 144);
                ah[2] = ldsu(qa + 16);
                ah[3] = ldsu(qa + 8 * 144 + 16);
                al[0] = ldsu(qa + QLB);
                al[1] = ldsu(qa + QLB + 8 * 144);
                al[2] = ldsu(qa + QLB + 16);
                al[3] = ldsu(qa + QLB + 8 * 144 + 16);
#pragma unroll
                for (int nt = 0; nt < 8; ++nt) {
                    const uint32_t ka = kb + (nt * 8 + g) * 144 + kk * 32 + t4 * 4;
                    uint32_t bh0 = ldsu(ka);
                    uint32_t bh1 = ldsu(ka + 16);
                    uint32_t bl0 = ldsu(ka + 9216);
                    uint32_t bl1 = ldsu(ka + 9216 + 16);
                    MMA4(sc[nt], ah, bh0, bh1);
                    MMA4(sc[nt], ah, bl0, bl1);
                    MMA4(sc[nt], al, bh0, bh1);
                }
            }

            // ---- causal mask ----
            if (j0 + 63 > rbase) {
                const int r0r = rbase + g, r1r = rbase + g + 8;
#pragma unroll
                for (int nt = 0; nt < 8; ++nt) {
#pragma unroll
                    for (int jj = 0; jj < 2; ++jj) {
                        const int col = j0 + nt * 8 + 2 * t4 + jj;
                        if (col > r0r) sc[nt][jj] = -1e30f;
                        if (col > r1r) sc[nt][2 + jj] = -1e30f;
                    }
                }
            }

            // ---- online softmax (rows g and g+8; reduce over lane quad) ----
            float mx0 = -1e30f, mx1 = -1e30f;
#pragma unroll
            for (int nt = 0; nt < 8; ++nt) {
                mx0 = fmaxf(mx0, fmaxf(sc[nt][0], sc[nt][1]));
                mx1 = fmaxf(mx1, fmaxf(sc[nt][2], sc[nt][3]));
            }
            mx0 = fmaxf(mx0, __shfl_xor_sync(0xffffffffu, mx0, 1));
            mx0 = fmaxf(mx0, __shfl_xor_sync(0xffffffffu, mx0, 2));
            mx1 = fmaxf(mx1, __shfl_xor_sync(0xffffffffu, mx1, 1));
            mx1 = fmaxf(mx1, __shfl_xor_sync(0xffffffffu, mx1, 2));

            const float mn0 = fmaxf(m0, mx0), mn1 = fmaxf(m1, mx1);
            const float a0 = __expf(m0 - mn0), a1 = __expf(m1 - mn1);
            m0 = mn0; m1 = mn1;

            float ps0 = 0.f, ps1 = 0.f;
#pragma unroll
            for (int nt = 0; nt < 8; ++nt) {
                sc[nt][0] = __expf(sc[nt][0] - mn0);
                sc[nt][1] = __expf(sc[nt][1] - mn0);
                sc[nt][2] = __expf(sc[nt][2] - mn1);
                sc[nt][3] = __expf(sc[nt][3] - mn1);
                ps0 += sc[nt][0] + sc[nt][1];
                ps1 += sc[nt][2] + sc[nt][3];
            }
            ps0 += __shfl_xor_sync(0xffffffffu, ps0, 1);
            ps0 += __shfl_xor_sync(0xffffffffu, ps0, 2);
            ps1 += __shfl_xor_sync(0xffffffffu, ps1, 1);
            ps1 += __shfl_xor_sync(0xffffffffu, ps1, 2);
            l0 = l0 * a0 + ps0;
            l1 = l1 * a1 + ps1;
#pragma unroll
            for (int nt = 0; nt < 8; ++nt) {
                o[nt][0] *= a0; o[nt][1] *= a0;
                o[nt][2] *= a1; o[nt][3] *= a1;
            }

            // ---- O += P V (bf16x3, P split in-register) ----
#pragma unroll
            for (int kk = 0; kk < 4; ++kk) {
                uint32_t ph[4], pl[4];
                splitpair(sc[2 * kk][0], sc[2 * kk][1], ph[0], pl[0]);
                splitpair(sc[2 * kk][2], sc[2 * kk][3], ph[1], pl[1]);
                splitpair(sc[2 * kk + 1][0], sc[2 * kk + 1][1], ph[2], pl[2]);
                splitpair(sc[2 * kk + 1][2], sc[2 * kk + 1][3], ph[3], pl[3]);
#pragma unroll
                for (int nt = 0; nt < 8; ++nt) {
                    const uint32_t va = kb + 18432 + (nt * 8 + g) * 144 + kk * 32 + t4 * 4;
                    uint32_t vh0 = ldsu(va);
                    uint32_t vh1 = ldsu(va + 16);
                    uint32_t vl0 = ldsu(va + 9216);
                    uint32_t vl1 = ldsu(va + 9216 + 16);
                    MMA4(o[nt], ph, vh0, vh1);
                    MMA4(o[nt], ph, vl0, vl1);
                    MMA4(o[nt], pl, vh0, vh1);
                }
            }
        }
        __syncthreads();
    }

    // ---- epilogue: normalize, write AO as bf16 hi/lo ----
    const float inv0 = 1.f / l0, inv1 = 1.f / l1;
    const size_t r0o = (base + rbase + g) * EMB + ch;
    const size_t r1o = (base + rbase + g + 8) * EMB + ch;
#pragma unroll
    for (int nt = 0; nt < 8; ++nt) {
        const int cc = nt * 8 + 2 * t4;
        uint32_t h01, l01, h23, l23;
        splitpair(o[nt][0] * inv0, o[nt][1] * inv0, h01, l01);
        splitpair(o[nt][2] * inv1, o[nt][3] * inv1, h23, l23);
        *(uint32_t*)(g_aoh + r0o + cc) = h01;
        *(uint32_t*)(g_aol + r0o + cc) = l01;
        *(uint32_t*)(g_aoh + r1o + cc) = h23;
        *(uint32_t*)(g_aol + r1o + cc) = l23;
    }
}

// ---------------------------------------------------------------------------
extern "C" void kernel_launch(void* const* d_in, const int* in_sizes, int n_in,
                              void* d_out, int out_size)
{
    (void)in_sizes; (void)n_in; (void)out_size;
    const float* x  = (const float*)d_in[0];
    const float* Wk = (const float*)d_in[1];
    const float* bk = (const float*)d_in[2];
    const float* Wq = (const float*)d_in[3];
    const float* bq = (const float*)d_in[4];
    const float* Wv = (const float*)d_in[5];
    const float* bv = (const float*)d_in[6];
    const float* Wo = (const float*)d_in[7];
    const float* bo = (const float*)d_in[8];

    cudaFuncSetAttribute(flash_mma_kernel,
                         cudaFuncAttributeMaxDynamicSharedMemorySize, FLASH_SMEM);
    cudaFuncSetAttribute(mma_qkv_kernel,
                         cudaFuncAttributeMaxDynamicSharedMemorySize, MMA_SMEM);
    cudaFuncSetAttribute(mma_out_kernel,
                         cudaFuncAttributeMaxDynamicSharedMemorySize, MMA_SMEM);

    split_x_kernel<<<4096, 256>>>(x);
    split_wt_kernel<<<dim3(32, 32, 4), 256>>>(Wq, Wk, Wv, Wo);
    mma_qkv_kernel<<<dim3(8, 32, 3), 256, MMA_SMEM>>>(bq, bk, bv);
    v_split_t_kernel<<<dim3(64, 32), 256>>>();
    flash_mma_kernel<<<dim3(16, 32), 256, FLASH_SMEM>>>();
    mma_out_kernel<<<dim3(8, 32), 256, MMA_SMEM>>>(bo, (float*)d_out);
}

// round 7
// speedup vs baseline: 3.6427x; 1.5669x over previous
#include <cuda_runtime.h>
#include <cstdint>

#define EMB   1024
#define CTXT  2048
#define MROWS 4096   // BATCH * CTXT
#define NH    16
#define HS    64

// ---------------------------------------------------------------------------
// Device scratch (allocation-free rule). All fp32, tf32-pre-rounded where noted.
// ---------------------------------------------------------------------------
__device__ float g_xr[MROWS * EMB];          // x, tf32-rounded
__device__ float g_wt[4][EMB * EMB];         // W^T [n][k], tf32-rounded (q,k,v,o)
__device__ float g_Qr[MROWS * EMB];          // (xWq+bq)/32, tf32-rounded
__device__ float g_Kr[MROWS * EMB];          // tf32-rounded
__device__ float g_V [MROWS * EMB];          // raw fp32
__device__ float g_Vt[MROWS * EMB];          // [bh][d][j], tf32-rounded
__device__ float g_aor[MROWS * EMB];         // attention out, tf32-rounded

// ---------------------------------------------------------------------------
__device__ __forceinline__ uint32_t smem_u32(const void* p) {
    uint32_t a;
    asm("{ .reg .u64 t; cvta.to.shared.u64 t, %1; cvt.u32.u64 %0, t; }"
        : "=r"(a) : "l"(p));
    return a;
}
__device__ __forceinline__ void cpa16(uint32_t s, const void* g) {
    asm volatile("cp.async.cg.shared.global [%0], [%1], 16;" :: "r"(s), "l"(g));
}
__device__ __forceinline__ uint32_t f2tf(float f) {
    uint32_t u;
    asm("cvt.rna.tf32.f32 %0, %1;" : "=r"(u) : "f"(f));
    return u;
}
__device__ __forceinline__ float roundtf(float f) { return __uint_as_float(f2tf(f)); }

#define LDM4(r, a)                                                            \
    asm volatile("ldmatrix.sync.aligned.m8n8.x4.shared.b16 {%0,%1,%2,%3}, [%4];" \
        : "=r"((r)[0]), "=r"((r)[1]), "=r"((r)[2]), "=r"((r)[3]) : "r"(a))

#define MMAT(c, a, b0, b1)                                                    \
    asm volatile("mma.sync.aligned.m16n8k8.row.col.f32.tf32.tf32.f32 "        \
        "{%0,%1,%2,%3}, {%4,%5,%6,%7}, {%8,%9}, {%0,%1,%2,%3};"               \
        : "+f"((c)[0]), "+f"((c)[1]), "+f"((c)[2]), "+f"((c)[3])              \
        : "r"((a)[0]), "r"((a)[1]), "r"((a)[2]), "r"((a)[3]), "r"(b0), "r"(b1))

// ---------------------------------------------------------------------------
// Prep kernels
// ---------------------------------------------------------------------------
__global__ __launch_bounds__(256) void round_x_kernel(const float* __restrict__ x) {
    int i = blockIdx.x * 256 + threadIdx.x;
    float4 v = *(const float4*)(x + (size_t)i * 4);
    v.x = roundtf(v.x); v.y = roundtf(v.y);
    v.z = roundtf(v.z); v.w = roundtf(v.w);
    *(float4*)(g_xr + (size_t)i * 4) = v;
}

__global__ __launch_bounds__(256) void round_wt_kernel(
    const float* __restrict__ Wq, const float* __restrict__ Wk,
    const float* __restrict__ Wv, const float* __restrict__ Wo)
{
    __shared__ float ts[32][33];
    const int z = blockIdx.z;
    const float* W = (z == 0) ? Wq : (z == 1) ? Wk : (z == 2) ? Wv : Wo;
    const int row0 = blockIdx.y << 5;   // k
    const int col0 = blockIdx.x << 5;   // n
    const int c = threadIdx.x & 31, r8 = threadIdx.x >> 5;
#pragma unroll
    for (int it = 0; it < 4; ++it) {
        int r = it * 8 + r8;
        ts[r][c] = W[(size_t)(row0 + r) * EMB + col0 + c];
    }
    __syncthreads();
#pragma unroll
    for (int it = 0; it < 4; ++it) {
        int r = it * 8 + r8;
        g_wt[z][(size_t)(col0 + r) * EMB + row0 + c] = roundtf(ts[c][r]);
    }
}

// V -> [bh][d][j], tf32-rounded
__global__ __launch_bounds__(256) void v_t_kernel() {
    __shared__ float ts[32][65];
    const int tid = threadIdx.x;
    const int bh = blockIdx.y, b = bh >> 4, h = bh & 15;
    const int j0 = blockIdx.x << 5;
    {
        int j = tid >> 3, dc = (tid & 7) << 3;
        const float* src = g_V + (size_t)(b * CTXT + j0 + j) * EMB + h * 64 + dc;
        float4 v0 = *(const float4*)src;
        float4 v1 = *(const float4*)(src + 4);
        ts[j][dc + 0] = v0.x; ts[j][dc + 1] = v0.y;
        ts[j][dc + 2] = v0.z; ts[j][dc + 3] = v0.w;
        ts[j][dc + 4] = v1.x; ts[j][dc + 5] = v1.y;
        ts[j][dc + 6] = v1.z; ts[j][dc + 7] = v1.w;
    }
    __syncthreads();
    {
        int d = tid >> 2, jq = (tid & 3) << 3;
        float4 o0, o1;
        o0.x = roundtf(ts[jq + 0][d]); o0.y = roundtf(ts[jq + 1][d]);
        o0.z = roundtf(ts[jq + 2][d]); o0.w = roundtf(ts[jq + 3][d]);
        o1.x = roundtf(ts[jq + 4][d]); o1.y = roundtf(ts[jq + 5][d]);
        o1.z = roundtf(ts[jq + 6][d]); o1.w = roundtf(ts[jq + 7][d]);
        size_t off = ((size_t)bh * 64 + d) * CTXT + j0 + jq;
        *(float4*)(g_Vt + off) = o0;
        *(float4*)(g_Vt + off + 4) = o1;
    }
}

// ---------------------------------------------------------------------------
// TF32 GEMM: C[128,128] tile, K=1024. 8 warps (4M x 2N), warp tile 32x64.
// BK=32 floats, 2-stage cp.async. smem rows 128B, chunk swizzle c^(r&7).
// ---------------------------------------------------------------------------
#define GBK 32
#define GSTAGE 32768                 // A 16KB + B 16KB
#define GEMM_SMEM (1024 + 2 * GSTAGE)

__device__ void tf32_gemm_body(const float* __restrict__ A,
                               const float* __restrict__ B,
                               const float* __restrict__ bias,
                               float* __restrict__ C,
                               int mode, float scale,   // mode 1: round(scale*v)
                               int row0, int col0)
{
    extern __shared__ char smraw[];
    const uint32_t sb = (smem_u32(smraw) + 1023u) & ~1023u;

    const int tid  = threadIdx.x;
    const int lane = tid & 31;
    const int wid  = tid >> 5;
    const int g    = lane >> 2;
    const int t4   = lane & 3;
    const int wm   = wid & 3;
    const int wn   = wid >> 2;

    float acc[2][8][4];
#pragma unroll
    for (int i = 0; i < 2; ++i)
#pragma unroll
        for (int j = 0; j < 8; ++j)
#pragma unroll
            for (int q = 0; q < 4; ++q) acc[i][j][q] = 0.f;

    // per-lane ldmatrix base addresses (XOR s<<5 per k8 step)
    uint32_t paA[2], paB[4];
    {
        const int rrA = (lane & 7) + ((lane >> 3) & 1) * 8;
        const int cpA = (lane >> 4) & 1;
#pragma unroll
        for (int ma = 0; ma < 2; ++ma) {
            int r = wm * 32 + ma * 16 + rrA;
            paA[ma] = r * 128 + ((cpA ^ (r & 1)) << 4) + (((r >> 1) & 3) << 5);
        }
        const int rrB = (lane & 7) + ((lane >> 4) & 1) * 8;
        const int cpB = (lane >> 3) & 1;
#pragma unroll
        for (int np = 0; np < 4; ++np) {
            int n = wn * 64 + np * 16 + rrB;
            paB[np] = 16384 + n * 128 + ((cpB ^ (n & 1)) << 4) + (((n >> 1) & 3) << 5);
        }
    }

    auto issue = [&](int kc, int st) {
        const uint32_t sbase = sb + st * GSTAGE;
#pragma unroll
        for (int it = 0; it < 8; ++it) {
            const int id = it * 256 + tid;     // 0..2047
            const int mat = id >> 10;          // 0=A, 1=B
            const int idx = id & 1023;
            const int r = idx >> 3, c = idx & 7;
            const float* src = (mat ? B + (size_t)(col0 + r) * EMB
                                    : A + (size_t)(row0 + r) * EMB) + kc + c * 4;
            cpa16(sbase + mat * 16384 + r * 128 + ((c ^ (r & 7)) << 4), src);
        }
        asm volatile("cp.async.commit_group;");
    };

    issue(0, 0);

    for (int c = 0; c < EMB / GBK; ++c) {
        if (c + 1 < EMB / GBK) {
            issue((c + 1) * GBK, (c + 1) & 1);
            asm volatile("cp.async.wait_group 1;");
        } else {
            asm volatile("cp.async.wait_group 0;");
        }
        __syncthreads();

        const uint32_t stb = sb + (c & 1) * GSTAGE;
#pragma unroll
        for (int s = 0; s < 4; ++s) {
            const uint32_t xs = (uint32_t)s << 5;
            uint32_t a[2][4], bg[4][4];
            LDM4(a[0], (stb + paA[0]) ^ xs);
            LDM4(a[1], (stb + paA[1]) ^ xs);
#pragma unroll
            for (int np = 0; np < 4; ++np) LDM4(bg[np], (stb + paB[np]) ^ xs);
#pragma unroll
            for (int nt = 0; nt < 8; ++nt) {
                const uint32_t b0 = bg[nt >> 1][(nt & 1) * 2];
                const uint32_t b1 = bg[nt >> 1][(nt & 1) * 2 + 1];
                MMAT(acc[0][nt], a[0], b0, b1);
                MMAT(acc[1][nt], a[1], b0, b1);
            }
        }
        __syncthreads();
    }

#pragma unroll
    for (int nt = 0; nt < 8; ++nt) {
        const int n = col0 + wn * 64 + nt * 8 + t4 * 2;
        const float bz0 = bias[n], bz1 = bias[n + 1];
#pragma unroll
        for (int ma = 0; ma < 2; ++ma) {
            const int mr = row0 + wm * 32 + ma * 16 + g;
            float p0 = acc[ma][nt][0] + bz0, p1 = acc[ma][nt][1] + bz1;
            float p2 = acc[ma][nt][2] + bz0, p3 = acc[ma][nt][3] + bz1;
            if (mode) {
                p0 = roundtf(p0 * scale); p1 = roundtf(p1 * scale);
                p2 = roundtf(p2 * scale); p3 = roundtf(p3 * scale);
            }
            *(float2*)(C + (size_t)mr * EMB + n) = float2{p0, p1};
            *(float2*)(C + (size_t)(mr + 8) * EMB + n) = float2{p2, p3};
        }
    }
}

__global__ __launch_bounds__(256) void gemm_qkv_kernel(
    const float* __restrict__ bq, const float* __restrict__ bk,
    const float* __restrict__ bv)
{
    const int z = blockIdx.z;
    const int r0 = blockIdx.y << 7, c0 = blockIdx.x << 7;
    if (z == 0)
        tf32_gemm_body(g_xr, g_wt[0], bq, g_Qr, 1, 0.03125f, r0, c0);
    else if (z == 1)
        tf32_gemm_body(g_xr, g_wt[1], bk, g_Kr, 1, 1.0f, r0, c0);
    else
        tf32_gemm_body(g_xr, g_wt[2], bv, g_V, 0, 1.0f, r0, c0);
}

__global__ __launch_bounds__(256) void gemm_out_kernel(
    const float* __restrict__ bo, float* __restrict__ out)
{
    tf32_gemm_body(g_aor, g_wt[3], bo, out, 0, 1.0f,
                   blockIdx.y << 7, blockIdx.x << 7);
}

// ---------------------------------------------------------------------------
// TF32 flash attention (causal, online softmax).
// BM=128 (8 warps x m16), BN=64, D=64. Grid: (T/128, B*H).
// smem: Q[128][64]f32 @0 (32KB); stages @32768+st*32768: K[64][64] + Vt[64][64].
// Rows 256B, chunk swizzle c^(r&7), c in 0..15.
// ---------------------------------------------------------------------------
#define FSTG0 32768
#define FSTGSZ 32768
#define FLASH_SMEM (1024 + FSTG0 + 2 * FSTGSZ)

__global__ __launch_bounds__(256) void flash_tf32_kernel()
{
    extern __shared__ char fsmraw[];
    const uint32_t sb = (smem_u32(fsmraw) + 1023u) & ~1023u;

    const int tid = threadIdx.x;
    const int lane = tid & 31, wid = tid >> 5;
    const int g = lane >> 2, t4 = lane & 3;
    const int bh = blockIdx.y, b = bh >> 4;
    const int qb = (int)(gridDim.x - 1 - blockIdx.x);   // longest first
    const int q0 = qb << 7;
    const size_t base = (size_t)b * CTXT;
    const int ch = (bh & 15) << 6;
    const int rbase = q0 + wid * 16;

    // ldmatrix per-lane bases (row stride 256B)
    uint32_t paQ, paB[4], paVoff[4];
    {
        const int rrA = (lane & 7) + ((lane >> 3) & 1) * 8;
        const int cpA = (lane >> 4) & 1;
        const int r = wid * 16 + rrA;
        paQ = r * 256 + ((cpA ^ (r & 1)) << 4) + (((r >> 1) & 3) << 5);

        const int rrB = (lane & 7) + ((lane >> 4) & 1) * 8;
        const int cpB = (lane >> 3) & 1;
#pragma unroll
        for (int np = 0; np < 4; ++np) {
            int n = np * 16 + rrB;
            uint32_t o = n * 256 + ((cpB ^ (n & 1)) << 4) + (((n >> 1) & 3) << 5);
            paB[np] = o;                 // K region (stage + 0)
            paVoff[np] = 16384 + o;      // Vt region
        }
    }

    // Q tile: 128 rows x 16 chunks
    for (int i = tid; i < 2048; i += 256) {
        const int r = i >> 4, c = i & 15;
        cpa16(sb + r * 256 + ((c ^ (r & 7)) << 4),
              g_Qr + (base + q0 + r) * EMB + ch + c * 4);
    }
    asm volatile("cp.async.commit_group;");

    auto issue_kv = [&](int j0, int st) {
        const uint32_t kb = sb + FSTG0 + st * FSTGSZ;
        for (int i = tid; i < 1024; i += 256) {
            const int r = i >> 4, c = i & 15;
            const uint32_t so = r * 256 + ((c ^ (r & 7)) << 4);
            cpa16(kb + so, g_Kr + (base + j0 + r) * EMB + ch + c * 4);
            cpa16(kb + 16384 + so,
                  g_Vt + ((size_t)bh * 64 + r) * CTXT + j0 + c * 4);
        }
        asm volatile("cp.async.commit_group;");
    };

    issue_kv(0, 0);

    float o[8][4];
#pragma unroll
    for (int nt = 0; nt < 8; ++nt)
#pragma unroll
        for (int q = 0; q < 4; ++q) o[nt][q] = 0.f;
    float m0 = -1e30f, m1 = -1e30f, l0 = 0.f, l1 = 0.f;

    const int nblocks = qb * 2 + 2;
    for (int jb = 0; jb < nblocks; ++jb) {
        const int j0 = jb << 6;
        if (jb + 1 < nblocks) {
            issue_kv((jb + 1) << 6, (jb + 1) & 1);
            asm volatile("cp.async.wait_group 1;");
        } else {
            asm volatile("cp.async.wait_group 0;");
        }
        __syncthreads();

        if (j0 <= rbase + 15) {
            const uint32_t kb = sb + FSTG0 + (jb & 1) * FSTGSZ;

            // ---- S = Q K^T ----
            float sc[8][4];
#pragma unroll
            for (int nt = 0; nt < 8; ++nt)
#pragma unroll
                for (int q = 0; q < 4; ++q) sc[nt][q] = 0.f;

#pragma unroll
            for (int s = 0; s < 8; ++s) {
                const uint32_t xs = (uint32_t)s << 5;
                uint32_t a[4], bg[4][4];
                LDM4(a, (sb + paQ) ^ xs);
#pragma unroll
                for (int np = 0; np < 4; ++np) LDM4(bg[np], (kb + paB[np]) ^ xs);
#pragma unroll
                for (int nt = 0; nt < 8; ++nt)
                    MMAT(sc[nt], a, bg[nt >> 1][(nt & 1) * 2],
                         bg[nt >> 1][(nt & 1) * 2 + 1]);
            }

            // ---- causal mask ----
            if (j0 + 63 > rbase) {
                const int r0r = rbase + g, r1r = rbase + g + 8;
#pragma unroll
                for (int nt = 0; nt < 8; ++nt) {
#pragma unroll
                    for (int jj = 0; jj < 2; ++jj) {
                        const int col = j0 + nt * 8 + 2 * t4 + jj;
                        if (col > r0r) sc[nt][jj] = -1e30f;
                        if (col > r1r) sc[nt][2 + jj] = -1e30f;
                    }
                }
            }

            // ---- online softmax (rows g, g+8; reduce over lane quad) ----
            float mx0 = -1e30f, mx1 = -1e30f;
#pragma unroll
            for (int nt = 0; nt < 8; ++nt) {
                mx0 = fmaxf(mx0, fmaxf(sc[nt][0], sc[nt][1]));
                mx1 = fmaxf(mx1, fmaxf(sc[nt][2], sc[nt][3]));
            }
            mx0 = fmaxf(mx0, __shfl_xor_sync(0xffffffffu, mx0, 1));
            mx0 = fmaxf(mx0, __shfl_xor_sync(0xffffffffu, mx0, 2));
            mx1 = fmaxf(mx1, __shfl_xor_sync(0xffffffffu, mx1, 1));
            mx1 = fmaxf(mx1, __shfl_xor_sync(0xffffffffu, mx1, 2));

            const float mn0 = fmaxf(m0, mx0), mn1 = fmaxf(m1, mx1);
            const float a0 = __expf(m0 - mn0), a1 = __expf(m1 - mn1);
            m0 = mn0; m1 = mn1;

            float ps0 = 0.f, ps1 = 0.f;
#pragma unroll
            for (int nt = 0; nt < 8; ++nt) {
                sc[nt][0] = __expf(sc[nt][0] - mn0);
                sc[nt][1] = __expf(sc[nt][1] - mn0);
                sc[nt][2] = __expf(sc[nt][2] - mn1);
                sc[nt][3] = __expf(sc[nt][3] - mn1);
                ps0 += sc[nt][0] + sc[nt][1];
                ps1 += sc[nt][2] + sc[nt][3];
            }
            ps0 += __shfl_xor_sync(0xffffffffu, ps0, 1);
            ps0 += __shfl_xor_sync(0xffffffffu, ps0, 2);
            ps1 += __shfl_xor_sync(0xffffffffu, ps1, 1);
            ps1 += __shfl_xor_sync(0xffffffffu, ps1, 2);
            l0 = l0 * a0 + ps0;
            l1 = l1 * a1 + ps1;
#pragma unroll
            for (int nt = 0; nt < 8; ++nt) {
                o[nt][0] *= a0; o[nt][1] *= a0;
                o[nt][2] *= a1; o[nt][3] *= a1;
            }

            // ---- O += P V : A-frag from S-frag via quad shuffles ----
            const int sl0 = (lane & 28) | (t4 >> 1);
            const int sl1 = sl0 | 2;
            const bool odd = (t4 & 1) != 0;
#pragma unroll
            for (int s = 0; s < 8; ++s) {   // k8 over j = s*8..s*8+7
                float f00 = __shfl_sync(0xffffffffu, sc[s][0], sl0);
                float f01 = __shfl_sync(0xffffffffu, sc[s][1], sl0);
                float f10 = __shfl_sync(0xffffffffu, sc[s][2], sl0);
                float f11 = __shfl_sync(0xffffffffu, sc[s][3], sl0);
                float h00 = __shfl_sync(0xffffffffu, sc[s][0], sl1);
                float h01 = __shfl_sync(0xffffffffu, sc[s][1], sl1);
                float h10 = __shfl_sync(0xffffffffu, sc[s][2], sl1);
                float h11 = __shfl_sync(0xffffffffu, sc[s][3], sl1);
                uint32_t ap[4];
                ap[0] = f2tf(odd ? f01 : f00);
                ap[1] = f2tf(odd ? f11 : f10);
                ap[2] = f2tf(odd ? h01 : h00);
                ap[3] = f2tf(odd ? h11 : h10);

                const uint32_t xs = (uint32_t)s << 5;
                uint32_t bg[4][4];
#pragma unroll
                for (int np = 0; np < 4; ++np) LDM4(bg[np], (kb + paVoff[np]) ^ xs);
#pragma unroll
                for (int nt = 0; nt < 8; ++nt)
                    MMAT(o[nt], ap, bg[nt >> 1][(nt & 1) * 2],
                         bg[nt >> 1][(nt & 1) * 2 + 1]);
            }
        }
        __syncthreads();
    }

    // ---- epilogue: normalize, tf32-round, write AO ----
    const float inv0 = 1.f / l0, inv1 = 1.f / l1;
    const size_t r0o = (base + rbase + g) * EMB + ch;
    const size_t r1o = (base + rbase + g + 8) * EMB + ch;
#pragma unroll
    for (int nt = 0; nt < 8; ++nt) {
        const int cc = nt * 8 + 2 * t4;
        *(float2*)(g_aor + r0o + cc) =
            float2{roundtf(o[nt][0] * inv0), roundtf(o[nt][1] * inv0)};
        *(float2*)(g_aor + r1o + cc) =
            float2{roundtf(o[nt][2] * inv1), roundtf(o[nt][3] * inv1)};
    }
}

// ---------------------------------------------------------------------------
extern "C" void kernel_launch(void* const* d_in, const int* in_sizes, int n_in,
                              void* d_out, int out_size)
{
    (void)in_sizes; (void)n_in; (void)out_size;
    const float* x  = (const float*)d_in[0];
    const float* Wk = (const float*)d_in[1];
    const float* bk = (const float*)d_in[2];
    const float* Wq = (const float*)d_in[3];
    const float* bq = (const float*)d_in[4];
    const float* Wv = (const float*)d_in[5];
    const float* bv = (const float*)d_in[6];
    const float* Wo = (const float*)d_in[7];
    const float* bo = (const float*)d_in[8];

    cudaFuncSetAttribute(flash_tf32_kernel,
                         cudaFuncAttributeMaxDynamicSharedMemorySize, FLASH_SMEM);
    cudaFuncSetAttribute(gemm_qkv_kernel,
                         cudaFuncAttributeMaxDynamicSharedMemorySize, GEMM_SMEM);
    cudaFuncSetAttribute(gemm_out_kernel,
                         cudaFuncAttributeMaxDynamicSharedMemorySize, GEMM_SMEM);

    round_x_kernel<<<4096, 256>>>(x);
    round_wt_kernel<<<dim3(32, 32, 4), 256>>>(Wq, Wk, Wv, Wo);
    gemm_qkv_kernel<<<dim3(8, 32, 3), 256, GEMM_SMEM>>>(bq, bk, bv);
    v_t_kernel<<<dim3(64, 32), 256>>>();
    flash_tf32_kernel<<<dim3(16, 32), 256, FLASH_SMEM>>>();
    gemm_out_kernel<<<dim3(8, 32), 256, GEMM_SMEM>>>(bo, (float*)d_out);
}

// round 8
// speedup vs baseline: 6.4267x; 1.7643x over previous
#include <cuda_runtime.h>
#include <cuda_fp16.h>
#include <cstdint>

#define EMB   1024
#define CTXT  2048
#define MROWS 4096   // BATCH * CTXT

// ---------------------------------------------------------------------------
// Device scratch (allocation-free rule)
// ---------------------------------------------------------------------------
__device__ __half g_xh[MROWS * EMB];         // x, fp16
__device__ __half g_wt[4][EMB * EMB];        // W^T [n][k] fp16 (q,k,v,o)
__device__ __half g_Qh[MROWS * EMB];         // (xWq+bq)/32 fp16
__device__ __half g_Kh[MROWS * EMB];         // fp16
__device__ float  g_V [MROWS * EMB];         // fp32
__device__ __half g_Vt[MROWS * EMB];         // [bh][d][j] fp16
__device__ __half g_ao[MROWS * EMB];         // attention out fp16

// ---------------------------------------------------------------------------
__device__ __forceinline__ uint32_t smem_u32(const void* p) {
    uint32_t a;
    asm("{ .reg .u64 t; cvta.to.shared.u64 t, %1; cvt.u32.u64 %0, t; }"
        : "=r"(a) : "l"(p));
    return a;
}
__device__ __forceinline__ void cpa16(uint32_t s, const void* g) {
    asm volatile("cp.async.cg.shared.global [%0], [%1], 16;" :: "r"(s), "l"(g));
}
__device__ __forceinline__ uint32_t packh(float x, float y) {
    __half2 h = __floats2half2_rn(x, y);
    return *(uint32_t*)&h;
}

#define LDM4(r, a)                                                            \
    asm volatile("ldmatrix.sync.aligned.m8n8.x4.shared.b16 {%0,%1,%2,%3}, [%4];" \
        : "=r"((r)[0]), "=r"((r)[1]), "=r"((r)[2]), "=r"((r)[3]) : "r"(a))

#define MMAH(c, a, b0, b1)                                                    \
    asm volatile("mma.sync.aligned.m16n8k16.row.col.f32.f16.f16.f32 "         \
        "{%0,%1,%2,%3}, {%4,%5,%6,%7}, {%8,%9}, {%0,%1,%2,%3};"               \
        : "+f"((c)[0]), "+f"((c)[1]), "+f"((c)[2]), "+f"((c)[3])              \
        : "r"((a)[0]), "r"((a)[1]), "r"((a)[2]), "r"((a)[3]), "r"(b0), "r"(b1))

// ---------------------------------------------------------------------------
// Prep kernels
// ---------------------------------------------------------------------------
__global__ __launch_bounds__(256) void conv_x_kernel(const float* __restrict__ x) {
    size_t i = ((size_t)blockIdx.x * 256 + threadIdx.x) * 8;
    float4 v0 = *(const float4*)(x + i);
    float4 v1 = *(const float4*)(x + i + 4);
    uint32_t h[4];
    h[0] = packh(v0.x, v0.y); h[1] = packh(v0.z, v0.w);
    h[2] = packh(v1.x, v1.y); h[3] = packh(v1.z, v1.w);
    *(uint4*)(g_xh + i) = *(uint4*)h;
}

// Transpose + convert weights: W[k][n] -> WT[n][k] fp16
__global__ __launch_bounds__(256) void conv_wt_kernel(
    const float* __restrict__ Wq, const float* __restrict__ Wk,
    const float* __restrict__ Wv, const float* __restrict__ Wo)
{
    __shared__ float ts[32][33];
    const int z = blockIdx.z;
    const float* W = (z == 0) ? Wq : (z == 1) ? Wk : (z == 2) ? Wv : Wo;
    const int row0 = blockIdx.y << 5;   // k
    const int col0 = blockIdx.x << 5;   // n
    const int c = threadIdx.x & 31, r8 = threadIdx.x >> 5;
#pragma unroll
    for (int it = 0; it < 4; ++it) {
        int r = it * 8 + r8;
        ts[r][c] = W[(size_t)(row0 + r) * EMB + col0 + c];
    }
    __syncthreads();
#pragma unroll
    for (int it = 0; it < 4; ++it) {
        int r = it * 8 + r8;
        g_wt[z][(size_t)(col0 + r) * EMB + row0 + c] = __float2half(ts[c][r]);
    }
}

// V (fp32, [token][h*64+d]) -> [bh][d][j] fp16
__global__ __launch_bounds__(256) void v_t_kernel() {
    __shared__ float ts[32][65];
    const int tid = threadIdx.x;
    const int bh = blockIdx.y, b = bh >> 4, h = bh & 15;
    const int j0 = blockIdx.x << 5;
    {
        int j = tid >> 3, dc = (tid & 7) << 3;
        const float* src = g_V + (size_t)(b * CTXT + j0 + j) * EMB + h * 64 + dc;
        float4 v0 = *(const float4*)src;
        float4 v1 = *(const float4*)(src + 4);
        ts[j][dc + 0] = v0.x; ts[j][dc + 1] = v0.y;
        ts[j][dc + 2] = v0.z; ts[j][dc + 3] = v0.w;
        ts[j][dc + 4] = v1.x; ts[j][dc + 5] = v1.y;
        ts[j][dc + 6] = v1.z; ts[j][dc + 7] = v1.w;
    }
    __syncthreads();
    {
        int d = tid >> 2, jq = (tid & 3) << 3;
        uint32_t p[4];
#pragma unroll
        for (int i = 0; i < 4; ++i)
            p[i] = packh(ts[jq + 2 * i][d], ts[jq + 2 * i + 1][d]);
        *(uint4*)(g_Vt + ((size_t)bh * 64 + d) * CTXT + j0 + jq) = *(uint4*)p;
    }
}

// ---------------------------------------------------------------------------
// FP16 GEMM: C[128,128] tile, K=1024. 8 warps (4M x 2N), warp tile 32x64.
// BK=64 halves (128B rows), 2-stage cp.async, chunk swizzle c^(r&7).
// ---------------------------------------------------------------------------
#define GSTAGE 32768                 // A 16KB + B 16KB
#define GEMM_SMEM (1024 + 2 * GSTAGE)

__device__ void h_gemm_body(const __half* __restrict__ A,
                            const __half* __restrict__ B,
                            const float* __restrict__ bias,
                            float* __restrict__ Cf,      // fp32 out (if non-null path)
                            __half* __restrict__ Ch,     // fp16 out
                            float scale,
                            int row0, int col0)
{
    extern __shared__ char smraw[];
    const uint32_t sb = (smem_u32(smraw) + 1023u) & ~1023u;

    const int tid  = threadIdx.x;
    const int lane = tid & 31;
    const int wid  = tid >> 5;
    const int g    = lane >> 2;
    const int t4   = lane & 3;
    const int wm   = wid & 3;
    const int wn   = wid >> 2;

    float acc[2][8][4];
#pragma unroll
    for (int i = 0; i < 2; ++i)
#pragma unroll
        for (int j = 0; j < 8; ++j)
#pragma unroll
            for (int q = 0; q < 4; ++q) acc[i][j][q] = 0.f;

    // per-lane ldmatrix bases (128B rows; XOR s<<5 per k16 step)
    uint32_t paA[2], paB[4];
    {
        const int rrA = (lane & 7) + ((lane >> 3) & 1) * 8;
        const int cpA = (lane >> 4) & 1;
#pragma unroll
        for (int ma = 0; ma < 2; ++ma) {
            int r = wm * 32 + ma * 16 + rrA;
            paA[ma] = r * 128 + ((cpA ^ (r & 1)) << 4) + (((r >> 1) & 3) << 5);
        }
        const int rrB = (lane & 7) + ((lane >> 4) & 1) * 8;
        const int cpB = (lane >> 3) & 1;
#pragma unroll
        for (int np = 0; np < 4; ++np) {
            int n = wn * 64 + np * 16 + rrB;
            paB[np] = 16384 + n * 128 + ((cpB ^ (n & 1)) << 4) + (((n >> 1) & 3) << 5);
        }
    }

    auto issue = [&](int kc, int st) {
        const uint32_t sbase = sb + st * GSTAGE;
#pragma unroll
        for (int it = 0; it < 8; ++it) {
            const int id = it * 256 + tid;     // 0..2047
            const int mat = id >> 10;          // 0=A, 1=B
            const int idx = id & 1023;
            const int r = idx >> 3, c = idx & 7;
            const __half* src = (mat ? B + (size_t)(col0 + r) * EMB
                                     : A + (size_t)(row0 + r) * EMB) + kc + c * 8;
            cpa16(sbase + mat * 16384 + r * 128 + ((c ^ (r & 7)) << 4), src);
        }
        asm volatile("cp.async.commit_group;");
    };

    issue(0, 0);

    for (int c = 0; c < EMB / 64; ++c) {
        if (c + 1 < EMB / 64) {
            issue((c + 1) * 64, (c + 1) & 1);
            asm volatile("cp.async.wait_group 1;");
        } else {
            asm volatile("cp.async.wait_group 0;");
        }
        __syncthreads();

        const uint32_t stb = sb + (c & 1) * GSTAGE;
#pragma unroll
        for (int s = 0; s < 4; ++s) {
            const uint32_t xs = (uint32_t)s << 5;
            uint32_t a[2][4], bg[4][4];
            LDM4(a[0], (stb + paA[0]) ^ xs);
            LDM4(a[1], (stb + paA[1]) ^ xs);
#pragma unroll
            for (int np = 0; np < 4; ++np) LDM4(bg[np], (stb + paB[np]) ^ xs);
#pragma unroll
            for (int nt = 0; nt < 8; ++nt) {
                const uint32_t b0 = bg[nt >> 1][(nt & 1) * 2];
                const uint32_t b1 = bg[nt >> 1][(nt & 1) * 2 + 1];
                MMAH(acc[0][nt], a[0], b0, b1);
                MMAH(acc[1][nt], a[1], b0, b1);
            }
        }
        __syncthreads();
    }

#pragma unroll
    for (int nt = 0; nt < 8; ++nt) {
        const int n = col0 + wn * 64 + nt * 8 + t4 * 2;
        const float bz0 = bias[n], bz1 = bias[n + 1];
#pragma unroll
        for (int ma = 0; ma < 2; ++ma) {
            const int mr = row0 + wm * 32 + ma * 16 + g;
            float p0 = acc[ma][nt][0] + bz0, p1 = acc[ma][nt][1] + bz1;
            float p2 = acc[ma][nt][2] + bz0, p3 = acc[ma][nt][3] + bz1;
            if (Ch) {
                *(uint32_t*)(Ch + (size_t)mr * EMB + n) = packh(p0 * scale, p1 * scale);
                *(uint32_t*)(Ch + (size_t)(mr + 8) * EMB + n) = packh(p2 * scale, p3 * scale);
            } else {
                *(float2*)(Cf + (size_t)mr * EMB + n) = float2{p0, p1};
                *(float2*)(Cf + (size_t)(mr + 8) * EMB + n) = float2{p2, p3};
            }
        }
    }
}

__global__ __launch_bounds__(256) void gemm_qkv_kernel(
    const float* __restrict__ bq, const float* __restrict__ bk,
    const float* __restrict__ bv)
{
    const int z = blockIdx.z;
    const int r0 = blockIdx.y << 7, c0 = blockIdx.x << 7;
    if (z == 0)
        h_gemm_body(g_xh, g_wt[0], bq, nullptr, g_Qh, 0.03125f, r0, c0);
    else if (z == 1)
        h_gemm_body(g_xh, g_wt[1], bk, nullptr, g_Kh, 1.0f, r0, c0);
    else
        h_gemm_body(g_xh, g_wt[2], bv, g_V, nullptr, 1.0f, r0, c0);
}

__global__ __launch_bounds__(256) void gemm_out_kernel(
    const float* __restrict__ bo, float* __restrict__ out)
{
    h_gemm_body(g_ao, g_wt[3], bo, out, nullptr, 1.0f,
                blockIdx.y << 7, blockIdx.x << 7);
}

// ---------------------------------------------------------------------------
// FP16 flash attention (causal, online softmax).
// BM=128 (8 warps x m16), BN=64, D=64. Grid: (T/128, B*H).
// smem: Q[128][64h] @0 (16KB); stages @16384+st*16384: K[64][64h] + Vt[64][64h].
// Rows 128B, chunk swizzle c^(r&7).
// ---------------------------------------------------------------------------
#define FSTG0 16384
#define FSTGSZ 16384
#define FLASH_SMEM (1024 + FSTG0 + 2 * FSTGSZ)

__global__ __launch_bounds__(256) void flash_h_kernel()
{
    extern __shared__ char fsmraw[];
    const uint32_t sb = (smem_u32(fsmraw) + 1023u) & ~1023u;

    const int tid = threadIdx.x;
    const int lane = tid & 31, wid = tid >> 5;
    const int g = lane >> 2, t4 = lane & 3;
    const int bh = blockIdx.y, b = bh >> 4;
    const int qb = (int)(gridDim.x - 1 - blockIdx.x);   // longest first
    const int q0 = qb << 7;
    const size_t base = (size_t)b * CTXT;
    const int ch = (bh & 15) << 6;
    const int rbase = q0 + wid * 16;

    // ldmatrix per-lane bases (row stride 128B)
    uint32_t paQ, paK[4], paV[4];
    {
        const int rrA = (lane & 7) + ((lane >> 3) & 1) * 8;
        const int cpA = (lane >> 4) & 1;
        const int r = wid * 16 + rrA;
        paQ = r * 128 + ((cpA ^ (r & 1)) << 4) + (((r >> 1) & 3) << 5);

        const int rrB = (lane & 7) + ((lane >> 4) & 1) * 8;
        const int cpB = (lane >> 3) & 1;
#pragma unroll
        for (int np = 0; np < 4; ++np) {
            int n = np * 16 + rrB;
            uint32_t o = n * 128 + ((cpB ^ (n & 1)) << 4) + (((n >> 1) & 3) << 5);
            paK[np] = o;
            paV[np] = 8192 + o;
        }
    }

    // Q tile: 128 rows x 8 chunks
    for (int i = tid; i < 1024; i += 256) {
        const int r = i >> 3, c = i & 7;
        cpa16(sb + r * 128 + ((c ^ (r & 7)) << 4),
              g_Qh + (base + q0 + r) * EMB + ch + c * 8);
    }
    asm volatile("cp.async.commit_group;");

    auto issue_kv = [&](int j0, int st) {
        const uint32_t kb = sb + FSTG0 + st * FSTGSZ;
        for (int i = tid; i < 512; i += 256) {
            const int r = i >> 3, c = i & 7;
            const uint32_t so = r * 128 + ((c ^ (r & 7)) << 4);
            cpa16(kb + so, g_Kh + (base + j0 + r) * EMB + ch + c * 8);
            cpa16(kb + 8192 + so,
                  g_Vt + ((size_t)bh * 64 + r) * CTXT + j0 + c * 8);
        }
        asm volatile("cp.async.commit_group;");
    };

    issue_kv(0, 0);

    float o[8][4];
#pragma unroll
    for (int nt = 0; nt < 8; ++nt)
#pragma unroll
        for (int q = 0; q < 4; ++q) o[nt][q] = 0.f;
    float m0 = -1e30f, m1 = -1e30f, l0 = 0.f, l1 = 0.f;

    const int nblocks = qb * 2 + 2;
    for (int jb = 0; jb < nblocks; ++jb) {
        const int j0 = jb << 6;
        if (jb + 1 < nblocks) {
            issue_kv((jb + 1) << 6, (jb + 1) & 1);
            asm volatile("cp.async.wait_group 1;");
        } else {
            asm volatile("cp.async.wait_group 0;");
        }
        __syncthreads();

        if (j0 <= rbase + 15) {
            const uint32_t kb = sb + FSTG0 + (jb & 1) * FSTGSZ;

            // ---- S = Q K^T ----
            float sc[8][4];
#pragma unroll
            for (int nt = 0; nt < 8; ++nt)
#pragma unroll
                for (int q = 0; q < 4; ++q) sc[nt][q] = 0.f;

#pragma unroll
            for (int s = 0; s < 4; ++s) {
                const uint32_t xs = (uint32_t)s << 5;
                uint32_t a[4], bg[4][4];
                LDM4(a, (sb + paQ) ^ xs);
#pragma unroll
                for (int np = 0; np < 4; ++np) LDM4(bg[np], (kb + paK[np]) ^ xs);
#pragma unroll
                for (int nt = 0; nt < 8; ++nt)
                    MMAH(sc[nt], a, bg[nt >> 1][(nt & 1) * 2],
                         bg[nt >> 1][(nt & 1) * 2 + 1]);
            }

            // ---- causal mask ----
            if (j0 + 63 > rbase) {
                const int r0r = rbase + g, r1r = rbase + g + 8;
#pragma unroll
                for (int nt = 0; nt < 8; ++nt) {
#pragma unroll
                    for (int jj = 0; jj < 2; ++jj) {
                        const int col = j0 + nt * 8 + 2 * t4 + jj;
                        if (col > r0r) sc[nt][jj] = -1e30f;
                        if (col > r1r) sc[nt][2 + jj] = -1e30f;
                    }
                }
            }

            // ---- online softmax (rows g, g+8; reduce over lane quad) ----
            float mx0 = -1e30f, mx1 = -1e30f;
#pragma unroll
            for (int nt = 0; nt < 8; ++nt) {
                mx0 = fmaxf(mx0, fmaxf(sc[nt][0], sc[nt][1]));
                mx1 = fmaxf(mx1, fmaxf(sc[nt][2], sc[nt][3]));
            }
            mx0 = fmaxf(mx0, __shfl_xor_sync(0xffffffffu, mx0, 1));
            mx0 = fmaxf(mx0, __shfl_xor_sync(0xffffffffu, mx0, 2));
            mx1 = fmaxf(mx1, __shfl_xor_sync(0xffffffffu, mx1, 1));
            mx1 = fmaxf(mx1, __shfl_xor_sync(0xffffffffu, mx1, 2));

            const float mn0 = fmaxf(m0, mx0), mn1 = fmaxf(m1, mx1);
            const float a0 = __expf(m0 - mn0), a1 = __expf(m1 - mn1);
            m0 = mn0; m1 = mn1;

            float ps0 = 0.f, ps1 = 0.f;
#pragma unroll
            for (int nt = 0; nt < 8; ++nt) {
                sc[nt][0] = __expf(sc[nt][0] - mn0);
                sc[nt][1] = __expf(sc[nt][1] - mn0);
                sc[nt][2] = __expf(sc[nt][2] - mn1);
                sc[nt][3] = __expf(sc[nt][3] - mn1);
                ps0 += sc[nt][0] + sc[nt][1];
                ps1 += sc[nt][2] + sc[nt][3];
            }
            ps0 += __shfl_xor_sync(0xffffffffu, ps0, 1);
            ps0 += __shfl_xor_sync(0xffffffffu, ps0, 2);
            ps1 += __shfl_xor_sync(0xffffffffu, ps1, 1);
            ps1 += __shfl_xor_sync(0xffffffffu, ps1, 2);
            l0 = l0 * a0 + ps0;
            l1 = l1 * a1 + ps1;
#pragma unroll
            for (int nt = 0; nt < 8; ++nt) {
                o[nt][0] *= a0; o[nt][1] *= a0;
                o[nt][2] *= a1; o[nt][3] *= a1;
            }

            // ---- O += P V : fp16 A-frags = packed S C-frags (no shuffles) ----
#pragma unroll
            for (int s = 0; s < 4; ++s) {   // k16 over j = 16s..16s+15
                uint32_t ap[4];
                ap[0] = packh(sc[2 * s][0], sc[2 * s][1]);
                ap[1] = packh(sc[2 * s][2], sc[2 * s][3]);
                ap[2] = packh(sc[2 * s + 1][0], sc[2 * s + 1][1]);
                ap[3] = packh(sc[2 * s + 1][2], sc[2 * s + 1][3]);

                const uint32_t xs = (uint32_t)s << 5;
                uint32_t bg[4][4];
#pragma unroll
                for (int np = 0; np < 4; ++np) LDM4(bg[np], (kb + paV[np]) ^ xs);
#pragma unroll
                for (int nt = 0; nt < 8; ++nt)
                    MMAH(o[nt], ap, bg[nt >> 1][(nt & 1) * 2],
                         bg[nt >> 1][(nt & 1) * 2 + 1]);
            }
        }
        __syncthreads();
    }

    // ---- epilogue: normalize, write AO fp16 ----
    const float inv0 = 1.f / l0, inv1 = 1.f / l1;
    const size_t r0o = (base + rbase + g) * EMB + ch;
    const size_t r1o = (base + rbase + g + 8) * EMB + ch;
#pragma unroll
    for (int nt = 0; nt < 8; ++nt) {
        const int cc = nt * 8 + 2 * t4;
        *(uint32_t*)(g_ao + r0o + cc) = packh(o[nt][0] * inv0, o[nt][1] * inv0);
        *(uint32_t*)(g_ao + r1o + cc) = packh(o[nt][2] * inv1, o[nt][3] * inv1);
    }
}

// ---------------------------------------------------------------------------
extern "C" void kernel_launch(void* const* d_in, const int* in_sizes, int n_in,
                              void* d_out, int out_size)
{
    (void)in_sizes; (void)n_in; (void)out_size;
    const float* x  = (const float*)d_in[0];
    const float* Wk = (const float*)d_in[1];
    const float* bk = (const float*)d_in[2];
    const float* Wq = (const float*)d_in[3];
    const float* bq = (const float*)d_in[4];
    const float* Wv = (const float*)d_in[5];
    const float* bv = (const float*)d_in[6];
    const float* Wo = (const float*)d_in[7];
    const float* bo = (const float*)d_in[8];

    cudaFuncSetAttribute(flash_h_kernel,
                         cudaFuncAttributeMaxDynamicSharedMemorySize, FLASH_SMEM);
    cudaFuncSetAttribute(gemm_qkv_kernel,
                         cudaFuncAttributeMaxDynamicSharedMemorySize, GEMM_SMEM);
    cudaFuncSetAttribute(gemm_out_kernel,
                         cudaFuncAttributeMaxDynamicSharedMemorySize, GEMM_SMEM);

    conv_x_kernel<<<2048, 256>>>(x);
    conv_wt_kernel<<<dim3(32, 32, 4), 256>>>(Wq, Wk, Wv, Wo);
    gemm_qkv_kernel<<<dim3(8, 32, 3), 256, GEMM_SMEM>>>(bq, bk, bv);
    v_t_kernel<<<dim3(64, 32), 256>>>();
    flash_h_kernel<<<dim3(16, 32), 256, FLASH_SMEM>>>();
    gemm_out_kernel<<<dim3(8, 32), 256, GEMM_SMEM>>>(bo, (float*)d_out);
}

// round 9
// speedup vs baseline: 6.6048x; 1.0277x over previous
#include <cuda_runtime.h>
#include <cuda_fp16.h>
#include <cstdint>

#define EMB   1024
#define CTXT  2048
#define MROWS 4096   // BATCH * CTXT

// ---------------------------------------------------------------------------
// Device scratch (allocation-free rule)
// ---------------------------------------------------------------------------
__device__ __half g_xh[MROWS * EMB];         // x, fp16
__device__ __half g_wt[4][EMB * EMB];        // W^T [n][k] fp16 (q,k,v,o)
__device__ __half g_Qh[MROWS * EMB];         // (xWq+bq)/32 fp16
__device__ __half g_Kh[MROWS * EMB];         // fp16
__device__ __half g_Vh[MROWS * EMB];         // fp16 (row-major, same layout as K)
__device__ __half g_ao[MROWS * EMB];         // attention out fp16

// ---------------------------------------------------------------------------
__device__ __forceinline__ uint32_t smem_u32(const void* p) {
    uint32_t a;
    asm("{ .reg .u64 t; cvta.to.shared.u64 t, %1; cvt.u32.u64 %0, t; }"
        : "=r"(a) : "l"(p));
    return a;
}
__device__ __forceinline__ void cpa16(uint32_t s, const void* g) {
    asm volatile("cp.async.cg.shared.global [%0], [%1], 16;" :: "r"(s), "l"(g));
}
__device__ __forceinline__ uint32_t packh(float x, float y) {
    __half2 h = __floats2half2_rn(x, y);
    return *(uint32_t*)&h;
}

#define LDM4(r, a)                                                            \
    asm volatile("ldmatrix.sync.aligned.m8n8.x4.shared.b16 {%0,%1,%2,%3}, [%4];" \
        : "=r"((r)[0]), "=r"((r)[1]), "=r"((r)[2]), "=r"((r)[3]) : "r"(a))

#define LDM4T(r, a)                                                           \
    asm volatile("ldmatrix.sync.aligned.m8n8.x4.trans.shared.b16 {%0,%1,%2,%3}, [%4];" \
        : "=r"((r)[0]), "=r"((r)[1]), "=r"((r)[2]), "=r"((r)[3]) : "r"(a))

#define MMAH(c, a, b0, b1)                                                    \
    asm volatile("mma.sync.aligned.m16n8k16.row.col.f32.f16.f16.f32 "         \
        "{%0,%1,%2,%3}, {%4,%5,%6,%7}, {%8,%9}, {%0,%1,%2,%3};"               \
        : "+f"((c)[0]), "+f"((c)[1]), "+f"((c)[2]), "+f"((c)[3])              \
        : "r"((a)[0]), "r"((a)[1]), "r"((a)[2]), "r"((a)[3]), "r"(b0), "r"(b1))

// ---------------------------------------------------------------------------
// Prep kernels
// ---------------------------------------------------------------------------
__global__ __launch_bounds__(256) void conv_x_kernel(const float* __restrict__ x) {
    size_t i = ((size_t)blockIdx.x * 256 + threadIdx.x) * 8;
    float4 v0 = *(const float4*)(x + i);
    float4 v1 = *(const float4*)(x + i + 4);
    uint32_t h[4];
    h[0] = packh(v0.x, v0.y); h[1] = packh(v0.z, v0.w);
    h[2] = packh(v1.x, v1.y); h[3] = packh(v1.z, v1.w);
    *(uint4*)(g_xh + i) = *(uint4*)h;
}

// Transpose + convert weights: W[k][n] -> WT[n][k] fp16
__global__ __launch_bounds__(256) void conv_wt_kernel(
    const float* __restrict__ Wq, const float* __restrict__ Wk,
    const float* __restrict__ Wv, const float* __restrict__ Wo)
{
    __shared__ float ts[32][33];
    const int z = blockIdx.z;
    const float* W = (z == 0) ? Wq : (z == 1) ? Wk : (z == 2) ? Wv : Wo;
    const int row0 = blockIdx.y << 5;   // k
    const int col0 = blockIdx.x << 5;   // n
    const int c = threadIdx.x & 31, r8 = threadIdx.x >> 5;
#pragma unroll
    for (int it = 0; it < 4; ++it) {
        int r = it * 8 + r8;
        ts[r][c] = W[(size_t)(row0 + r) * EMB + col0 + c];
    }
    __syncthreads();
#pragma unroll
    for (int it = 0; it < 4; ++it) {
        int r = it * 8 + r8;
        g_wt[z][(size_t)(col0 + r) * EMB + row0 + c] = __float2half(ts[c][r]);
    }
}

// ---------------------------------------------------------------------------
// FP16 GEMM: C[128,128] tile, K=1024. 8 warps (4M x 2N), warp tile 32x64.
// BK=64 halves (128B rows), 3-stage cp.async, single sync per chunk.
// ---------------------------------------------------------------------------
#define GSTAGE 32768                 // A 16KB + B 16KB
#define GEMM_SMEM (1024 + 3 * GSTAGE)

__device__ void h_gemm_body(const __half* __restrict__ A,
                            const __half* __restrict__ B,
                            const float* __restrict__ bias,
                            float* __restrict__ Cf,      // fp32 out
                            __half* __restrict__ Ch,     // fp16 out
                            float scale,
                            int row0, int col0)
{
    extern __shared__ char smraw[];
    const uint32_t sb = (smem_u32(smraw) + 1023u) & ~1023u;

    const int tid  = threadIdx.x;
    const int lane = tid & 31;
    const int wid  = tid >> 5;
    const int g    = lane >> 2;
    const int t4   = lane & 3;
    const int wm   = wid & 3;
    const int wn   = wid >> 2;

    float acc[2][8][4];
#pragma unroll
    for (int i = 0; i < 2; ++i)
#pragma unroll
        for (int j = 0; j < 8; ++j)
#pragma unroll
            for (int q = 0; q < 4; ++q) acc[i][j][q] = 0.f;

    // per-lane ldmatrix bases (128B rows; XOR s<<5 per k16 step)
    uint32_t paA[2], paB[4];
    {
        const int rrA = (lane & 7) + ((lane >> 3) & 1) * 8;
        const int cpA = (lane >> 4) & 1;
#pragma unroll
        for (int ma = 0; ma < 2; ++ma) {
            int r = wm * 32 + ma * 16 + rrA;
            paA[ma] = r * 128 + ((cpA ^ (r & 1)) << 4) + (((r >> 1) & 3) << 5);
        }
        const int rrB = (lane & 7) + ((lane >> 4) & 1) * 8;
        const int cpB = (lane >> 3) & 1;
#pragma unroll
        for (int np = 0; np < 4; ++np) {
            int n = wn * 64 + np * 16 + rrB;
            paB[np] = 16384 + n * 128 + ((cpB ^ (n & 1)) << 4) + (((n >> 1) & 3) << 5);
        }
    }

    auto issue = [&](int kc, int st) {
        const uint32_t sbase = sb + st * GSTAGE;
#pragma unroll
        for (int it = 0; it < 8; ++it) {
            const int id = it * 256 + tid;     // 0..2047
            const int mat = id >> 10;          // 0=A, 1=B
            const int idx = id & 1023;
            const int r = idx >> 3, c = idx & 7;
            const __half* src = (mat ? B + (size_t)(col0 + r) * EMB
                                     : A + (size_t)(row0 + r) * EMB) + kc + c * 8;
            cpa16(sbase + mat * 16384 + r * 128 + ((c ^ (r & 7)) << 4), src);
        }
        asm volatile("cp.async.commit_group;");
    };

    issue(0, 0);
    issue(64, 1);

    for (int c = 0; c < EMB / 64; ++c) {
        if (c + 1 < EMB / 64) {
            asm volatile("cp.async.wait_group 1;");
        } else {
            asm volatile("cp.async.wait_group 0;");
        }
        __syncthreads();
        if (c + 2 < EMB / 64) issue((c + 2) * 64, (c + 2) % 3);

        const uint32_t stb = sb + (c % 3) * GSTAGE;
#pragma unroll
        for (int s = 0; s < 4; ++s) {
            const uint32_t xs = (uint32_t)s << 5;
            uint32_t a[2][4], bg[4][4];
            LDM4(a[0], (stb + paA[0]) ^ xs);
            LDM4(a[1], (stb + paA[1]) ^ xs);
#pragma unroll
            for (int np = 0; np < 4; ++np) LDM4(bg[np], (stb + paB[np]) ^ xs);
#pragma unroll
            for (int nt = 0; nt < 8; ++nt) {
                const uint32_t b0 = bg[nt >> 1][(nt & 1) * 2];
                const uint32_t b1 = bg[nt >> 1][(nt & 1) * 2 + 1];
                MMAH(acc[0][nt], a[0], b0, b1);
                MMAH(acc[1][nt], a[1], b0, b1);
            }
        }
    }

#pragma unroll
    for (int nt = 0; nt < 8; ++nt) {
        const int n = col0 + wn * 64 + nt * 8 + t4 * 2;
        const float bz0 = bias[n], bz1 = bias[n + 1];
#pragma unroll
        for (int ma = 0; ma < 2; ++ma) {
            const int mr = row0 + wm * 32 + ma * 16 + g;
            float p0 = acc[ma][nt][0] + bz0, p1 = acc[ma][nt][1] + bz1;
            float p2 = acc[ma][nt][2] + bz0, p3 = acc[ma][nt][3] + bz1;
            if (Ch) {
                *(uint32_t*)(Ch + (size_t)mr * EMB + n) = packh(p0 * scale, p1 * scale);
                *(uint32_t*)(Ch + (size_t)(mr + 8) * EMB + n) = packh(p2 * scale, p3 * scale);
            } else {
                *(float2*)(Cf + (size_t)mr * EMB + n) = float2{p0, p1};
                *(float2*)(Cf + (size_t)(mr + 8) * EMB + n) = float2{p2, p3};
            }
        }
    }
}

__global__ __launch_bounds__(256) void gemm_qkv_kernel(
    const float* __restrict__ bq, const float* __restrict__ bk,
    const float* __restrict__ bv)
{
    const int z = blockIdx.z;
    const int r0 = blockIdx.y << 7, c0 = blockIdx.x << 7;
    if (z == 0)
        h_gemm_body(g_xh, g_wt[0], bq, nullptr, g_Qh, 0.03125f, r0, c0);
    else if (z == 1)
        h_gemm_body(g_xh, g_wt[1], bk, nullptr, g_Kh, 1.0f, r0, c0);
    else
        h_gemm_body(g_xh, g_wt[2], bv, nullptr, g_Vh, 1.0f, r0, c0);
}

__global__ __launch_bounds__(256) void gemm_out_kernel(
    const float* __restrict__ bo, float* __restrict__ out)
{
    h_gemm_body(g_ao, g_wt[3], bo, out, nullptr, 1.0f,
                blockIdx.y << 7, blockIdx.x << 7);
}

// ---------------------------------------------------------------------------
// FP16 flash attention (causal, online softmax).
// BM=128 (8 warps x m16), BN=64, D=64. Grid: (T/128, B*H).
// smem: Q[128][64h] @0 (16KB); 3 KV stages @16384+st*16384: K[64][64h]+V[64][64h].
// V stays row-major [j][d]; PV B-frags via ldmatrix.trans.
// ---------------------------------------------------------------------------
#define FSTG0 16384
#define FSTGSZ 16384
#define FLASH_SMEM (1024 + FSTG0 + 3 * FSTGSZ)

__global__ __launch_bounds__(256) void flash_h_kernel()
{
    extern __shared__ char fsmraw[];
    const uint32_t sb = (smem_u32(fsmraw) + 1023u) & ~1023u;

    const int tid = threadIdx.x;
    const int lane = tid & 31, wid = tid >> 5;
    const int g = lane >> 2, t4 = lane & 3;
    const int bh = blockIdx.y, b = bh >> 4;
    const int qb = (int)(gridDim.x - 1 - blockIdx.x);   // longest first
    const int q0 = qb << 7;
    const size_t base = (size_t)b * CTXT;
    const int ch = (bh & 15) << 6;
    const int rbase = q0 + wid * 16;

    // ldmatrix per-lane bases (row stride 128B)
    uint32_t paQ, paK[4], paVt[4];
    {
        const int rrA = (lane & 7) + ((lane >> 3) & 1) * 8;
        const int cpA = (lane >> 4) & 1;
        const int r = wid * 16 + rrA;
        paQ = r * 128 + ((cpA ^ (r & 1)) << 4) + (((r >> 1) & 3) << 5);

        const int rrB = (lane & 7) + ((lane >> 4) & 1) * 8;
        const int cpB = (lane >> 3) & 1;
#pragma unroll
        for (int np = 0; np < 4; ++np) {
            int n = np * 16 + rrB;
            paK[np] = n * 128 + ((cpB ^ (n & 1)) << 4) + (((n >> 1) & 3) << 5);
        }
        // V (trans): tiles {j, j+8} x {d, d+8}; lanes 0-7:t0, 8-15:t1, 16-23:t2, 24-31:t3
        const int rrV = (lane & 7) + ((lane >> 3) & 1) * 8;   // j within 16
        const int cpV = (lane >> 4) & 1;                      // d chunk within 16
#pragma unroll
        for (int np = 0; np < 4; ++np) {
            int c = 2 * np + cpV;
            paVt[np] = 8192 + rrV * 128 + ((c ^ (rrV & 7)) << 4);
        }
    }

    // Q tile: 128 rows x 8 chunks (group 0)
    for (int i = tid; i < 1024; i += 256) {
        const int r = i >> 3, c = i & 7;
        cpa16(sb + r * 128 + ((c ^ (r & 7)) << 4),
              g_Qh + (base + q0 + r) * EMB + ch + c * 8);
    }
    asm volatile("cp.async.commit_group;");

    auto issue_kv = [&](int j0, int st) {
        const uint32_t kb = sb + FSTG0 + st * FSTGSZ;
        for (int i = tid; i < 512; i += 256) {
            const int r = i >> 3, c = i & 7;
            const uint32_t so = r * 128 + ((c ^ (r & 7)) << 4);
            cpa16(kb + so, g_Kh + (base + j0 + r) * EMB + ch + c * 8);
            cpa16(kb + 8192 + so, g_Vh + (base + j0 + r) * EMB + ch + c * 8);
        }
        asm volatile("cp.async.commit_group;");
    };

    const int nblocks = qb * 2 + 2;
    issue_kv(0, 0);
    issue_kv(64, 1);

    float o[8][4];
#pragma unroll
    for (int nt = 0; nt < 8; ++nt)
#pragma unroll
        for (int q = 0; q < 4; ++q) o[nt][q] = 0.f;
    float m0 = -1e30f, m1 = -1e30f, l0 = 0.f, l1 = 0.f;

    for (int jb = 0; jb < nblocks; ++jb) {
        const int j0 = jb << 6;
        if (jb + 1 < nblocks) {
            asm volatile("cp.async.wait_group 1;");
        } else {
            asm volatile("cp.async.wait_group 0;");
        }
        __syncthreads();
        if (jb + 2 < nblocks) issue_kv((jb + 2) << 6, (jb + 2) % 3);

        if (j0 <= rbase + 15) {
            const uint32_t kb = sb + FSTG0 + (jb % 3) * FSTGSZ;

            // ---- S = Q K^T ----
            float sc[8][4];
#pragma unroll
            for (int nt = 0; nt < 8; ++nt)
#pragma unroll
                for (int q = 0; q < 4; ++q) sc[nt][q] = 0.f;

#pragma unroll
            for (int s = 0; s < 4; ++s) {
                const uint32_t xs = (uint32_t)s << 5;
                uint32_t a[4], bg[4][4];
                LDM4(a, (sb + paQ) ^ xs);
#pragma unroll
                for (int np = 0; np < 4; ++np) LDM4(bg[np], (kb + paK[np]) ^ xs);
#pragma unroll
                for (int nt = 0; nt < 8; ++nt)
                    MMAH(sc[nt], a, bg[nt >> 1][(nt & 1) * 2],
                         bg[nt >> 1][(nt & 1) * 2 + 1]);
            }

            // ---- causal mask ----
            if (j0 + 63 > rbase) {
                const int r0r = rbase + g, r1r = rbase + g + 8;
#pragma unroll
                for (int nt = 0; nt < 8; ++nt) {
#pragma unroll
                    for (int jj = 0; jj < 2; ++jj) {
                        const int col = j0 + nt * 8 + 2 * t4 + jj;
                        if (col > r0r) sc[nt][jj] = -1e30f;
                        if (col > r1r) sc[nt][2 + jj] = -1e30f;
                    }
                }
            }

            // ---- online softmax (rows g, g+8; reduce over lane quad) ----
            float mx0 = -1e30f, mx1 = -1e30f;
#pragma unroll
            for (int nt = 0; nt < 8; ++nt) {
                mx0 = fmaxf(mx0, fmaxf(sc[nt][0], sc[nt][1]));
                mx1 = fmaxf(mx1, fmaxf(sc[nt][2], sc[nt][3]));
            }
            mx0 = fmaxf(mx0, __shfl_xor_sync(0xffffffffu, mx0, 1));
            mx0 = fmaxf(mx0, __shfl_xor_sync(0xffffffffu, mx0, 2));
            mx1 = fmaxf(mx1, __shfl_xor_sync(0xffffffffu, mx1, 1));
            mx1 = fmaxf(mx1, __shfl_xor_sync(0xffffffffu, mx1, 2));

            const float mn0 = fmaxf(m0, mx0), mn1 = fmaxf(m1, mx1);
            const float a0 = __expf(m0 - mn0), a1 = __expf(m1 - mn1);
            m0 = mn0; m1 = mn1;

            float ps0 = 0.f, ps1 = 0.f;
#pragma unroll
            for (int nt = 0; nt < 8; ++nt) {
                sc[nt][0] = __expf(sc[nt][0] - mn0);
                sc[nt][1] = __expf(sc[nt][1] - mn0);
                sc[nt][2] = __expf(sc[nt][2] - mn1);
                sc[nt][3] = __expf(sc[nt][3] - mn1);
                ps0 += sc[nt][0] + sc[nt][1];
                ps1 += sc[nt][2] + sc[nt][3];
            }
            ps0 += __shfl_xor_sync(0xffffffffu, ps0, 1);
            ps0 += __shfl_xor_sync(0xffffffffu, ps0, 2);
            ps1 += __shfl_xor_sync(0xffffffffu, ps1, 1);
            ps1 += __shfl_xor_sync(0xffffffffu, ps1, 2);
            l0 = l0 * a0 + ps0;
            l1 = l1 * a1 + ps1;
#pragma unroll
            for (int nt = 0; nt < 8; ++nt) {
                o[nt][0] *= a0; o[nt][1] *= a0;
                o[nt][2] *= a1; o[nt][3] *= a1;
            }

            // ---- O += P V : A-frags packed from S; B-frags via ldmatrix.trans ----
#pragma unroll
            for (int s = 0; s < 4; ++s) {   // k16 over j = 16s..16s+15
                uint32_t ap[4];
                ap[0] = packh(sc[2 * s][0], sc[2 * s][1]);
                ap[1] = packh(sc[2 * s][2], sc[2 * s][3]);
                ap[2] = packh(sc[2 * s + 1][0], sc[2 * s + 1][1]);
                ap[3] = packh(sc[2 * s + 1][2], sc[2 * s + 1][3]);

                const uint32_t ro = (uint32_t)s * 2048;   // +16 rows per k16 step
                uint32_t bg[4][4];
#pragma unroll
                for (int np = 0; np < 4; ++np) LDM4T(bg[np], kb + paVt[np] + ro);
#pragma unroll
                for (int nt = 0; nt < 8; ++nt)
                    MMAH(o[nt], ap, bg[nt >> 1][(nt & 1) * 2],
                         bg[nt >> 1][(nt & 1) * 2 + 1]);
            }
        }
    }

    // ---- epilogue: normalize, write AO fp16 ----
    const float inv0 = 1.f / l0, inv1 = 1.f / l1;
    const size_t r0o = (base + rbase + g) * EMB + ch;
    const size_t r1o = (base + rbase + g + 8) * EMB + ch;
#pragma unroll
    for (int nt = 0; nt < 8; ++nt) {
        const int cc = nt * 8 + 2 * t4;
        *(uint32_t*)(g_ao + r0o + cc) = packh(o[nt][0] * inv0, o[nt][1] * inv0);
        *(uint32_t*)(g_ao + r1o + cc) = packh(o[nt][2] * inv1, o[nt][3] * inv1);
    }
}

// ---------------------------------------------------------------------------
extern "C" void kernel_launch(void* const* d_in, const int* in_sizes, int n_in,
                              void* d_out, int out_size)
{
    (void)in_sizes; (void)n_in; (void)out_size;
    const float* x  = (const float*)d_in[0];
    const float* Wk = (const float*)d_in[1];
    const float* bk = (const float*)d_in[2];
    const float* Wq = (const float*)d_in[3];
    const float* bq = (const float*)d_in[4];
    const float* Wv = (const float*)d_in[5];
    const float* bv = (const float*)d_in[6];
    const float* Wo = (const float*)d_in[7];
    const float* bo = (const float*)d_in[8];

    cudaFuncSetAttribute(flash_h_kernel,
                         cudaFuncAttributeMaxDynamicSharedMemorySize, FLASH_SMEM);
    cudaFuncSetAttribute(gemm_qkv_kernel,
                         cudaFuncAttributeMaxDynamicSharedMemorySize, GEMM_SMEM);
    cudaFuncSetAttribute(gemm_out_kernel,
                         cudaFuncAttributeMaxDynamicSharedMemorySize, GEMM_SMEM);

    conv_x_kernel<<<2048, 256>>>(x);
    conv_wt_kernel<<<dim3(32, 32, 4), 256>>>(Wq, Wk, Wv, Wo);
    gemm_qkv_kernel<<<dim3(8, 32, 3), 256, GEMM_SMEM>>>(bq, bk, bv);
    flash_h_kernel<<<dim3(16, 32), 256, FLASH_SMEM>>>();
    gemm_out_kernel<<<dim3(8, 32), 256, GEMM_SMEM>>>(bo, (float*)d_out);
}

// round 10
// speedup vs baseline: 6.8407x; 1.0357x over previous
#include <cuda_runtime.h>
#include <cuda_fp16.h>
#include <cstdint>

#define EMB   1024
#define CTXT  2048
#define MROWS 4096   // BATCH * CTXT

// ---------------------------------------------------------------------------
// Device scratch (allocation-free rule)
// ---------------------------------------------------------------------------
__device__ __half g_xh[MROWS * EMB];         // x, fp16
__device__ __half g_wt[4][EMB * EMB];        // W^T [n][k] fp16 (q,k,v,o)
__device__ __half g_Qh[MROWS * EMB];         // (xWq+bq) * log2e/32, fp16
__device__ __half g_Kh[MROWS * EMB];         // fp16
__device__ __half g_Vh[MROWS * EMB];         // fp16 (row-major)
__device__ __half g_ao[MROWS * EMB];         // attention out fp16

// ---------------------------------------------------------------------------
__device__ __forceinline__ uint32_t smem_u32(const void* p) {
    uint32_t a;
    asm("{ .reg .u64 t; cvta.to.shared.u64 t, %1; cvt.u32.u64 %0, t; }"
        : "=r"(a) : "l"(p));
    return a;
}
__device__ __forceinline__ void cpa16(uint32_t s, const void* g) {
    asm volatile("cp.async.cg.shared.global [%0], [%1], 16;" :: "r"(s), "l"(g));
}
__device__ __forceinline__ uint32_t packh(float x, float y) {
    __half2 h = __floats2half2_rn(x, y);
    return *(uint32_t*)&h;
}
// pack two fp32 (<=0) and take 2^x in fp16x2
__device__ __forceinline__ uint32_t ex2pack(float x, float y) {
    uint32_t d = packh(x, y), r;
    asm("ex2.approx.f16x2 %0, %1;" : "=r"(r) : "r"(d));
    return r;
}

#define LDM4(r, a)                                                            \
    asm volatile("ldmatrix.sync.aligned.m8n8.x4.shared.b16 {%0,%1,%2,%3}, [%4];" \
        : "=r"((r)[0]), "=r"((r)[1]), "=r"((r)[2]), "=r"((r)[3]) : "r"(a))

#define LDM4T(r, a)                                                           \
    asm volatile("ldmatrix.sync.aligned.m8n8.x4.trans.shared.b16 {%0,%1,%2,%3}, [%4];" \
        : "=r"((r)[0]), "=r"((r)[1]), "=r"((r)[2]), "=r"((r)[3]) : "r"(a))

#define MMAH(c, a, b0, b1)                                                    \
    asm volatile("mma.sync.aligned.m16n8k16.row.col.f32.f16.f16.f32 "         \
        "{%0,%1,%2,%3}, {%4,%5,%6,%7}, {%8,%9}, {%0,%1,%2,%3};"               \
        : "+f"((c)[0]), "+f"((c)[1]), "+f"((c)[2]), "+f"((c)[3])              \
        : "r"((a)[0]), "r"((a)[1]), "r"((a)[2]), "r"((a)[3]), "r"(b0), "r"(b1))

// ---------------------------------------------------------------------------
// Prep kernels
// ---------------------------------------------------------------------------
__global__ __launch_bounds__(256) void conv_x_kernel(const float* __restrict__ x) {
    size_t i = ((size_t)blockIdx.x * 256 + threadIdx.x) * 8;
    float4 v0 = *(const float4*)(x + i);
    float4 v1 = *(const float4*)(x + i + 4);
    uint32_t h[4];
    h[0] = packh(v0.x, v0.y); h[1] = packh(v0.z, v0.w);
    h[2] = packh(v1.x, v1.y); h[3] = packh(v1.z, v1.w);
    *(uint4*)(g_xh + i) = *(uint4*)h;
}

// Transpose + convert weights: W[k][n] -> WT[n][k] fp16
__global__ __launch_bounds__(256) void conv_wt_kernel(
    const float* __restrict__ Wq, const float* __restrict__ Wk,
    const float* __restrict__ Wv, const float* __restrict__ Wo)
{
    __shared__ float ts[32][33];
    const int z = blockIdx.z;
    const float* W = (z == 0) ? Wq : (z == 1) ? Wk : (z == 2) ? Wv : Wo;
    const int row0 = blockIdx.y << 5;   // k
    const int col0 = blockIdx.x << 5;   // n
    const int c = threadIdx.x & 31, r8 = threadIdx.x >> 5;
#pragma unroll
    for (int it = 0; it < 4; ++it) {
        int r = it * 8 + r8;
        ts[r][c] = W[(size_t)(row0 + r) * EMB + col0 + c];
    }
    __syncthreads();
#pragma unroll
    for (int it = 0; it < 4; ++it) {
        int r = it * 8 + r8;
        g_wt[z][(size_t)(col0 + r) * EMB + row0 + c] = __float2half(ts[c][r]);
    }
}

// ---------------------------------------------------------------------------
// FP16 GEMM: C[128,128] tile, K=1024. 8 warps (4M x 2N), warp tile 32x64.
// BK=64 halves (128B rows), 3-stage cp.async, single sync per chunk.
// ---------------------------------------------------------------------------
#define GSTAGE 32768                 // A 16KB + B 16KB
#define GEMM_SMEM (1024 + 3 * GSTAGE)

__device__ void h_gemm_body(const __half* __restrict__ A,
                            const __half* __restrict__ B,
                            const float* __restrict__ bias,
                            float* __restrict__ Cf,      // fp32 out
                            __half* __restrict__ Ch,     // fp16 out
                            float scale,
                            int row0, int col0)
{
    extern __shared__ char smraw[];
    const uint32_t sb = (smem_u32(smraw) + 1023u) & ~1023u;

    const int tid  = threadIdx.x;
    const int lane = tid & 31;
    const int wid  = tid >> 5;
    const int g    = lane >> 2;
    const int t4   = lane & 3;
    const int wm   = wid & 3;
    const int wn   = wid >> 2;

    float acc[2][8][4];
#pragma unroll
    for (int i = 0; i < 2; ++i)
#pragma unroll
        for (int j = 0; j < 8; ++j)
#pragma unroll
            for (int q = 0; q < 4; ++q) acc[i][j][q] = 0.f;

    uint32_t paA[2], paB[4];
    {
        const int rrA = (lane & 7) + ((lane >> 3) & 1) * 8;
        const int cpA = (lane >> 4) & 1;
#pragma unroll
        for (int ma = 0; ma < 2; ++ma) {
            int r = wm * 32 + ma * 16 + rrA;
            paA[ma] = r * 128 + ((cpA ^ (r & 1)) << 4) + (((r >> 1) & 3) << 5);
        }
        const int rrB = (lane & 7) + ((lane >> 4) & 1) * 8;
        const int cpB = (lane >> 3) & 1;
#pragma unroll
        for (int np = 0; np < 4; ++np) {
            int n = wn * 64 + np * 16 + rrB;
            paB[np] = 16384 + n * 128 + ((cpB ^ (n & 1)) << 4) + (((n >> 1) & 3) << 5);
        }
    }

    auto issue = [&](int kc, int st) {
        const uint32_t sbase = sb + st * GSTAGE;
#pragma unroll
        for (int it = 0; it < 8; ++it) {
            const int id = it * 256 + tid;
            const int mat = id >> 10;
            const int idx = id & 1023;
            const int r = idx >> 3, c = idx & 7;
            const __half* src = (mat ? B + (size_t)(col0 + r) * EMB
                                     : A + (size_t)(row0 + r) * EMB) + kc + c * 8;
            cpa16(sbase + mat * 16384 + r * 128 + ((c ^ (r & 7)) << 4), src);
        }
        asm volatile("cp.async.commit_group;");
    };

    issue(0, 0);
    issue(64, 1);

    for (int c = 0; c < EMB / 64; ++c) {
        if (c + 1 < EMB / 64) {
            asm volatile("cp.async.wait_group 1;");
        } else {
            asm volatile("cp.async.wait_group 0;");
        }
        __syncthreads();
        if (c + 2 < EMB / 64) issue((c + 2) * 64, (c + 2) % 3);

        const uint32_t stb = sb + (c % 3) * GSTAGE;
#pragma unroll
        for (int s = 0; s < 4; ++s) {
            const uint32_t xs = (uint32_t)s << 5;
            uint32_t a[2][4], bg[4][4];
            LDM4(a[0], (stb + paA[0]) ^ xs);
            LDM4(a[1], (stb + paA[1]) ^ xs);
#pragma unroll
            for (int np = 0; np < 4; ++np) LDM4(bg[np], (stb + paB[np]) ^ xs);
#pragma unroll
            for (int nt = 0; nt < 8; ++nt) {
                const uint32_t b0 = bg[nt >> 1][(nt & 1) * 2];
                const uint32_t b1 = bg[nt >> 1][(nt & 1) * 2 + 1];
                MMAH(acc[0][nt], a[0], b0, b1);
                MMAH(acc[1][nt], a[1], b0, b1);
            }
        }
    }

#pragma unroll
    for (int nt = 0; nt < 8; ++nt) {
        const int n = col0 + wn * 64 + nt * 8 + t4 * 2;
        const float bz0 = bias[n], bz1 = bias[n + 1];
#pragma unroll
        for (int ma = 0; ma < 2; ++ma) {
            const int mr = row0 + wm * 32 + ma * 16 + g;
            float p0 = acc[ma][nt][0] + bz0, p1 = acc[ma][nt][1] + bz1;
            float p2 = acc[ma][nt][2] + bz0, p3 = acc[ma][nt][3] + bz1;
            if (Ch) {
                *(uint32_t*)(Ch + (size_t)mr * EMB + n) = packh(p0 * scale, p1 * scale);
                *(uint32_t*)(Ch + (size_t)(mr + 8) * EMB + n) = packh(p2 * scale, p3 * scale);
            } else {
                *(float2*)(Cf + (size_t)mr * EMB + n) = float2{p0, p1};
                *(float2*)(Cf + (size_t)(mr + 8) * EMB + n) = float2{p2, p3};
            }
        }
    }
}

__global__ __launch_bounds__(256) void gemm_qkv_kernel(
    const float* __restrict__ bq, const float* __restrict__ bk,
    const float* __restrict__ bv)
{
    const int z = blockIdx.z;
    const int r0 = blockIdx.y << 7, c0 = blockIdx.x << 7;
    if (z == 0)   // fold 1/sqrt(1024) * log2(e) into Q
        h_gemm_body(g_xh, g_wt[0], bq, nullptr, g_Qh, 0.0450842190f, r0, c0);
    else if (z == 1)
        h_gemm_body(g_xh, g_wt[1], bk, nullptr, g_Kh, 1.0f, r0, c0);
    else
        h_gemm_body(g_xh, g_wt[2], bv, nullptr, g_Vh, 1.0f, r0, c0);
}

__global__ __launch_bounds__(256) void gemm_out_kernel(
    const float* __restrict__ bo, float* __restrict__ out)
{
    h_gemm_body(g_ao, g_wt[3], bo, out, nullptr, 1.0f,
                blockIdx.y << 7, blockIdx.x << 7);
}

// ---------------------------------------------------------------------------
// FP16 flash attention, log2-domain softmax, fp16x2 ex2, ones-MMA row sums.
// BM=128 (8 warps x m16), BN=64, D=64. Grid: (T/128, B*H).
// smem: Q[128][64h] @0 (16KB); 3 KV stages: K[64][64h]+V[64][64h] each 16KB.
// ---------------------------------------------------------------------------
#define FSTG0 16384
#define FSTGSZ 16384
#define FLASH_SMEM (1024 + FSTG0 + 3 * FSTGSZ)
#define HONES 0x3C003C00u   // half2(1.0, 1.0)

__global__ __launch_bounds__(256) void flash_h_kernel()
{
    extern __shared__ char fsmraw[];
    const uint32_t sb = (smem_u32(fsmraw) + 1023u) & ~1023u;

    const int tid = threadIdx.x;
    const int lane = tid & 31, wid = tid >> 5;
    const int g = lane >> 2, t4 = lane & 3;
    const int bh = blockIdx.y, b = bh >> 4;
    const int qb = (int)(gridDim.x - 1 - blockIdx.x);   // longest first
    const int q0 = qb << 7;
    const size_t base = (size_t)b * CTXT;
    const int ch = (bh & 15) << 6;
    const int rbase = q0 + wid * 16;

    uint32_t paQ, paK[4], paVt[4];
    {
        const int rrA = (lane & 7) + ((lane >> 3) & 1) * 8;
        const int cpA = (lane >> 4) & 1;
        const int r = wid * 16 + rrA;
        paQ = r * 128 + ((cpA ^ (r & 1)) << 4) + (((r >> 1) & 3) << 5);

        const int rrB = (lane & 7) + ((lane >> 4) & 1) * 8;
        const int cpB = (lane >> 3) & 1;
#pragma unroll
        for (int np = 0; np < 4; ++np) {
            int n = np * 16 + rrB;
            paK[np] = n * 128 + ((cpB ^ (n & 1)) << 4) + (((n >> 1) & 3) << 5);
        }
        const int rrV = (lane & 7) + ((lane >> 3) & 1) * 8;   // j within 16
        const int cpV = (lane >> 4) & 1;                      // d chunk within 16
#pragma unroll
        for (int np = 0; np < 4; ++np) {
            int c = 2 * np + cpV;
            paVt[np] = 8192 + rrV * 128 + ((c ^ (rrV & 7)) << 4);
        }
    }

    for (int i = tid; i < 1024; i += 256) {
        const int r = i >> 3, c = i & 7;
        cpa16(sb + r * 128 + ((c ^ (r & 7)) << 4),
              g_Qh + (base + q0 + r) * EMB + ch + c * 8);
    }
    asm volatile("cp.async.commit_group;");

    auto issue_kv = [&](int j0, int st) {
        const uint32_t kb = sb + FSTG0 + st * FSTGSZ;
        for (int i = tid; i < 512; i += 256) {
            const int r = i >> 3, c = i & 7;
            const uint32_t so = r * 128 + ((c ^ (r & 7)) << 4);
            cpa16(kb + so, g_Kh + (base + j0 + r) * EMB + ch + c * 8);
            cpa16(kb + 8192 + so, g_Vh + (base + j0 + r) * EMB + ch + c * 8);
        }
        asm volatile("cp.async.commit_group;");
    };

    const int nblocks = qb * 2 + 2;
    issue_kv(0, 0);
    issue_kv(64, 1);

    float o[8][4];
    float ol[4] = {0.f, 0.f, 0.f, 0.f};    // ones-column row sums (l in [0]/[2])
#pragma unroll
    for (int nt = 0; nt < 8; ++nt)
#pragma unroll
        for (int q = 0; q < 4; ++q) o[nt][q] = 0.f;
    float m0 = -1e30f, m1 = -1e30f;

    for (int jb = 0; jb < nblocks; ++jb) {
        const int j0 = jb << 6;
        if (jb + 1 < nblocks) {
            asm volatile("cp.async.wait_group 1;");
        } else {
            asm volatile("cp.async.wait_group 0;");
        }
        __syncthreads();
        if (jb + 2 < nblocks) issue_kv((jb + 2) << 6, (jb + 2) % 3);

        if (j0 <= rbase + 15) {
            const uint32_t kb = sb + FSTG0 + (jb % 3) * FSTGSZ;

            // ---- S = Q K^T  (already in log2 units) ----
            float sc[8][4];
#pragma unroll
            for (int nt = 0; nt < 8; ++nt)
#pragma unroll
                for (int q = 0; q < 4; ++q) sc[nt][q] = 0.f;

#pragma unroll
            for (int s = 0; s < 4; ++s) {
                const uint32_t xs = (uint32_t)s << 5;
                uint32_t a[4], bg[4][4];
                LDM4(a, (sb + paQ) ^ xs);
#pragma unroll
                for (int np = 0; np < 4; ++np) LDM4(bg[np], (kb + paK[np]) ^ xs);
#pragma unroll
                for (int nt = 0; nt < 8; ++nt)
                    MMAH(sc[nt], a, bg[nt >> 1][(nt & 1) * 2],
                         bg[nt >> 1][(nt & 1) * 2 + 1]);
            }

            // ---- causal mask ----
            if (j0 + 63 > rbase) {
                const int r0r = rbase + g, r1r = rbase + g + 8;
#pragma unroll
                for (int nt = 0; nt < 8; ++nt) {
#pragma unroll
                    for (int jj = 0; jj < 2; ++jj) {
                        const int col = j0 + nt * 8 + 2 * t4 + jj;
                        if (col > r0r) sc[nt][jj] = -1e30f;
                        if (col > r1r) sc[nt][2 + jj] = -1e30f;
                    }
                }
            }

            // ---- online softmax (log2 domain) ----
            float mx0 = -1e30f, mx1 = -1e30f;
#pragma unroll
            for (int nt = 0; nt < 8; ++nt) {
                mx0 = fmaxf(mx0, fmaxf(sc[nt][0], sc[nt][1]));
                mx1 = fmaxf(mx1, fmaxf(sc[nt][2], sc[nt][3]));
            }
            mx0 = fmaxf(mx0, __shfl_xor_sync(0xffffffffu, mx0, 1));
            mx0 = fmaxf(mx0, __shfl_xor_sync(0xffffffffu, mx0, 2));
            mx1 = fmaxf(mx1, __shfl_xor_sync(0xffffffffu, mx1, 1));
            mx1 = fmaxf(mx1, __shfl_xor_sync(0xffffffffu, mx1, 2));

            const float mn0 = fmaxf(m0, mx0), mn1 = fmaxf(m1, mx1);
            const float a0 = exp2f(m0 - mn0), a1 = exp2f(m1 - mn1);
            m0 = mn0; m1 = mn1;

#pragma unroll
            for (int nt = 0; nt < 8; ++nt) {
                o[nt][0] *= a0; o[nt][1] *= a0;
                o[nt][2] *= a1; o[nt][3] *= a1;
            }
            ol[0] *= a0; ol[1] *= a0; ol[2] *= a1; ol[3] *= a1;

            // ---- O += P V ; l += P * 1 (P = 2^(s-m) in fp16, direct A-frags) ----
#pragma unroll
            for (int s = 0; s < 4; ++s) {   // k16 over j = 16s..16s+15
                uint32_t ap[4];
                ap[0] = ex2pack(sc[2 * s][0] - mn0, sc[2 * s][1] - mn0);
                ap[1] = ex2pack(sc[2 * s][2] - mn1, sc[2 * s][3] - mn1);
                ap[2] = ex2pack(sc[2 * s + 1][0] - mn0, sc[2 * s + 1][1] - mn0);
                ap[3] = ex2pack(sc[2 * s + 1][2] - mn1, sc[2 * s + 1][3] - mn1);

                MMAH(ol, ap, HONES, HONES);   // row sums

                const uint32_t ro = (uint32_t)s * 2048;
                uint32_t bg[4][4];
#pragma unroll
                for (int np = 0; np < 4; ++np) LDM4T(bg[np], kb + paVt[np] + ro);
#pragma unroll
                for (int nt = 0; nt < 8; ++nt)
                    MMAH(o[nt], ap, bg[nt >> 1][(nt & 1) * 2],
                         bg[nt >> 1][(nt & 1) * 2 + 1]);
            }
        }
    }

    // ---- epilogue: normalize, write AO fp16 ----
    const float inv0 = 1.f / ol[0], inv1 = 1.f / ol[2];
    const size_t r0o = (base + rbase + g) * EMB + ch;
    const size_t r1o = (base + rbase + g + 8) * EMB + ch;
#pragma unroll
    for (int nt = 0; nt < 8; ++nt) {
        const int cc = nt * 8 + 2 * t4;
        *(uint32_t*)(g_ao + r0o + cc) = packh(o[nt][0] * inv0, o[nt][1] * inv0);
        *(uint32_t*)(g_ao + r1o + cc) = packh(o[nt][2] * inv1, o[nt][3] * inv1);
    }
}

// ---------------------------------------------------------------------------
extern "C" void kernel_launch(void* const* d_in, const int* in_sizes, int n_in,
                              void* d_out, int out_size)
{
    (void)in_sizes; (void)n_in; (void)out_size;
    const float* x  = (const float*)d_in[0];
    const float* Wk = (const float*)d_in[1];
    const float* bk = (const float*)d_in[2];
    const float* Wq = (const float*)d_in[3];
    const float* bq = (const float*)d_in[4];
    const float* Wv = (const float*)d_in[5];
    const float* bv = (const float*)d_in[6];
    const float* Wo = (const float*)d_in[7];
    const float* bo = (const float*)d_in[8];

    cudaFuncSetAttribute(flash_h_kernel,
                         cudaFuncAttributeMaxDynamicSharedMemorySize, FLASH_SMEM);
    cudaFuncSetAttribute(gemm_qkv_kernel,
                         cudaFuncAttributeMaxDynamicSharedMemorySize, GEMM_SMEM);
    cudaFuncSetAttribute(gemm_out_kernel,
                         cudaFuncAttributeMaxDynamicSharedMemorySize, GEMM_SMEM);

    conv_x_kernel<<<2048, 256>>>(x);
    conv_wt_kernel<<<dim3(32, 32, 4), 256>>>(Wq, Wk, Wv, Wo);
    gemm_qkv_kernel<<<dim3(8, 32, 3), 256, GEMM_SMEM>>>(bq, bk, bv);
    flash_h_kernel<<<dim3(16, 32), 256, FLASH_SMEM>>>();
    gemm_out_kernel<<<dim3(8, 32), 256, GEMM_SMEM>>>(bo, (float*)d_out);
}

// round 11
// speedup vs baseline: 7.2046x; 1.0532x over previous
#include <cuda_runtime.h>
#include <cuda_fp16.h>
#include <cstdint>

#define EMB   1024
#define CTXT  2048
#define MROWS 4096   // BATCH * CTXT

// ---------------------------------------------------------------------------
// Device scratch (allocation-free rule)
// ---------------------------------------------------------------------------
__device__ __half g_xh[MROWS * EMB];         // x, fp16
__device__ __half g_wt[4][EMB * EMB];        // W^T [n][k] fp16 (q,k,v,o)
__device__ __half g_Qh[MROWS * EMB];         // (xWq+bq) * log2e/32, fp16
__device__ __half g_Kh[MROWS * EMB];         // fp16
__device__ __half g_Vh[MROWS * EMB];         // fp16 (row-major)
__device__ __half g_ao[MROWS * EMB];         // attention out fp16

// ---------------------------------------------------------------------------
__device__ __forceinline__ uint32_t smem_u32(const void* p) {
    uint32_t a;
    asm("{ .reg .u64 t; cvta.to.shared.u64 t, %1; cvt.u32.u64 %0, t; }"
        : "=r"(a) : "l"(p));
    return a;
}
__device__ __forceinline__ void cpa16(uint32_t s, const void* g) {
    asm volatile("cp.async.cg.shared.global [%0], [%1], 16;" :: "r"(s), "l"(g));
}
__device__ __forceinline__ uint32_t packh(float x, float y) {
    __half2 h = __floats2half2_rn(x, y);
    return *(uint32_t*)&h;
}
// pack two fp32 (<=0) and take 2^x in fp16x2
__device__ __forceinline__ uint32_t ex2pack(float x, float y) {
    uint32_t d = packh(x, y), r;
    asm("ex2.approx.f16x2 %0, %1;" : "=r"(r) : "r"(d));
    return r;
}

#define LDM4(r, a)                                                            \
    asm volatile("ldmatrix.sync.aligned.m8n8.x4.shared.b16 {%0,%1,%2,%3}, [%4];" \
        : "=r"((r)[0]), "=r"((r)[1]), "=r"((r)[2]), "=r"((r)[3]) : "r"(a))

#define LDM4T(r, a)                                                           \
    asm volatile("ldmatrix.sync.aligned.m8n8.x4.trans.shared.b16 {%0,%1,%2,%3}, [%4];" \
        : "=r"((r)[0]), "=r"((r)[1]), "=r"((r)[2]), "=r"((r)[3]) : "r"(a))

#define MMAH(c, a, b0, b1)                                                    \
    asm volatile("mma.sync.aligned.m16n8k16.row.col.f32.f16.f16.f32 "         \
        "{%0,%1,%2,%3}, {%4,%5,%6,%7}, {%8,%9}, {%0,%1,%2,%3};"               \
        : "+f"((c)[0]), "+f"((c)[1]), "+f"((c)[2]), "+f"((c)[3])              \
        : "r"((a)[0]), "r"((a)[1]), "r"((a)[2]), "r"((a)[3]), "r"(b0), "r"(b1))

// ---------------------------------------------------------------------------
// Prep kernels
// ---------------------------------------------------------------------------
__global__ __launch_bounds__(256) void conv_x_kernel(const float* __restrict__ x) {
    size_t i = ((size_t)blockIdx.x * 256 + threadIdx.x) * 8;
    float4 v0 = *(const float4*)(x + i);
    float4 v1 = *(const float4*)(x + i + 4);
    uint32_t h[4];
    h[0] = packh(v0.x, v0.y); h[1] = packh(v0.z, v0.w);
    h[2] = packh(v1.x, v1.y); h[3] = packh(v1.z, v1.w);
    *(uint4*)(g_xh + i) = *(uint4*)h;
}

// Transpose + convert weights: W[k][n] -> WT[n][k] fp16
__global__ __launch_bounds__(256) void conv_wt_kernel(
    const float* __restrict__ Wq, const float* __restrict__ Wk,
    const float* __restrict__ Wv, const float* __restrict__ Wo)
{
    __shared__ float ts[32][33];
    const int z = blockIdx.z;
    const float* W = (z == 0) ? Wq : (z == 1) ? Wk : (z == 2) ? Wv : Wo;
    const int row0 = blockIdx.y << 5;   // k
    const int col0 = blockIdx.x << 5;   // n
    const int c = threadIdx.x & 31, r8 = threadIdx.x >> 5;
#pragma unroll
    for (int it = 0; it < 4; ++it) {
        int r = it * 8 + r8;
        ts[r][c] = W[(size_t)(row0 + r) * EMB + col0 + c];
    }
    __syncthreads();
#pragma unroll
    for (int it = 0; it < 4; ++it) {
        int r = it * 8 + r8;
        g_wt[z][(size_t)(col0 + r) * EMB + row0 + c] = __float2half(ts[c][r]);
    }
}

// ---------------------------------------------------------------------------
// FP16 GEMM: C[128,128] tile, K=1024. 8 warps (4M x 2N), warp tile 32x64.
// BK=64 halves (128B rows), 3-stage cp.async, single sync per chunk.
// ---------------------------------------------------------------------------
#define GSTAGE 32768                 // A 16KB + B 16KB
#define GEMM_SMEM (1024 + 3 * GSTAGE)

__device__ void h_gemm_body(const __half* __restrict__ A,
                            const __half* __restrict__ B,
                            const float* __restrict__ bias,
                            float* __restrict__ Cf,      // fp32 out
                            __half* __restrict__ Ch,     // fp16 out
                            float scale,
                            int row0, int col0)
{
    extern __shared__ char smraw[];
    const uint32_t sb = (smem_u32(smraw) + 1023u) & ~1023u;

    const int tid  = threadIdx.x;
    const int lane = tid & 31;
    const int wid  = tid >> 5;
    const int g    = lane >> 2;
    const int t4   = lane & 3;
    const int wm   = wid & 3;
    const int wn   = wid >> 2;

    float acc[2][8][4];
#pragma unroll
    for (int i = 0; i < 2; ++i)
#pragma unroll
        for (int j = 0; j < 8; ++j)
#pragma unroll
            for (int q = 0; q < 4; ++q) acc[i][j][q] = 0.f;

    uint32_t paA[2], paB[4];
    {
        const int rrA = (lane & 7) + ((lane >> 3) & 1) * 8;
        const int cpA = (lane >> 4) & 1;
#pragma unroll
        for (int ma = 0; ma < 2; ++ma) {
            int r = wm * 32 + ma * 16 + rrA;
            paA[ma] = r * 128 + ((cpA ^ (r & 1)) << 4) + (((r >> 1) & 3) << 5);
        }
        const int rrB = (lane & 7) + ((lane >> 4) & 1) * 8;
        const int cpB = (lane >> 3) & 1;
#pragma unroll
        for (int np = 0; np < 4; ++np) {
            int n = wn * 64 + np * 16 + rrB;
            paB[np] = 16384 + n * 128 + ((cpB ^ (n & 1)) << 4) + (((n >> 1) & 3) << 5);
        }
    }

    auto issue = [&](int kc, int st) {
        const uint32_t sbase = sb + st * GSTAGE;
#pragma unroll
        for (int it = 0; it < 8; ++it) {
            const int id = it * 256 + tid;
            const int mat = id >> 10;
            const int idx = id & 1023;
            const int r = idx >> 3, c = idx & 7;
            const __half* src = (mat ? B + (size_t)(col0 + r) * EMB
                                     : A + (size_t)(row0 + r) * EMB) + kc + c * 8;
            cpa16(sbase + mat * 16384 + r * 128 + ((c ^ (r & 7)) << 4), src);
        }
        asm volatile("cp.async.commit_group;");
    };

    issue(0, 0);
    issue(64, 1);

    for (int c = 0; c < EMB / 64; ++c) {
        if (c + 1 < EMB / 64) {
            asm volatile("cp.async.wait_group 1;");
        } else {
            asm volatile("cp.async.wait_group 0;");
        }
        __syncthreads();
        if (c + 2 < EMB / 64) issue((c + 2) * 64, (c + 2) % 3);

        const uint32_t stb = sb + (c % 3) * GSTAGE;
#pragma unroll
        for (int s = 0; s < 4; ++s) {
            const uint32_t xs = (uint32_t)s << 5;
            uint32_t a[2][4], bg[4][4];
            LDM4(a[0], (stb + paA[0]) ^ xs);
            LDM4(a[1], (stb + paA[1]) ^ xs);
#pragma unroll
            for (int np = 0; np < 4; ++np) LDM4(bg[np], (stb + paB[np]) ^ xs);
#pragma unroll
            for (int nt = 0; nt < 8; ++nt) {
                const uint32_t b0 = bg[nt >> 1][(nt & 1) * 2];
                const uint32_t b1 = bg[nt >> 1][(nt & 1) * 2 + 1];
                MMAH(acc[0][nt], a[0], b0, b1);
                MMAH(acc[1][nt], a[1], b0, b1);
            }
        }
    }

#pragma unroll
    for (int nt = 0; nt < 8; ++nt) {
        const int n = col0 + wn * 64 + nt * 8 + t4 * 2;
        const float bz0 = bias[n], bz1 = bias[n + 1];
#pragma unroll
        for (int ma = 0; ma < 2; ++ma) {
            const int mr = row0 + wm * 32 + ma * 16 + g;
            float p0 = acc[ma][nt][0] + bz0, p1 = acc[ma][nt][1] + bz1;
            float p2 = acc[ma][nt][2] + bz0, p3 = acc[ma][nt][3] + bz1;
            if (Ch) {
                *(uint32_t*)(Ch + (size_t)mr * EMB + n) = packh(p0 * scale, p1 * scale);
                *(uint32_t*)(Ch + (size_t)(mr + 8) * EMB + n) = packh(p2 * scale, p3 * scale);
            } else {
                *(float2*)(Cf + (size_t)mr * EMB + n) = float2{p0, p1};
                *(float2*)(Cf + (size_t)(mr + 8) * EMB + n) = float2{p2, p3};
            }
        }
    }
}

__global__ __launch_bounds__(256) void gemm_qkv_kernel(
    const float* __restrict__ bq, const float* __restrict__ bk,
    const float* __restrict__ bv)
{
    const int z = blockIdx.z;
    const int r0 = blockIdx.y << 7, c0 = blockIdx.x << 7;
    if (z == 0)   // fold 1/sqrt(1024) * log2(e) into Q
        h_gemm_body(g_xh, g_wt[0], bq, nullptr, g_Qh, 0.0450842190f, r0, c0);
    else if (z == 1)
        h_gemm_body(g_xh, g_wt[1], bk, nullptr, g_Kh, 1.0f, r0, c0);
    else
        h_gemm_body(g_xh, g_wt[2], bv, nullptr, g_Vh, 1.0f, r0, c0);
}

__global__ __launch_bounds__(256) void gemm_out_kernel(
    const float* __restrict__ bo, float* __restrict__ out)
{
    h_gemm_body(g_ao, g_wt[3], bo, out, nullptr, 1.0f,
                blockIdx.y << 7, blockIdx.x << 7);
}

// ---------------------------------------------------------------------------
// FP16 flash attention, log2-domain softmax, fp16x2 ex2, ones-MMA row sums.
// BM=128 (8 warps x m16), BN=64, D=64. Grid: (T/128, B*H).
// smem: Q[128][64h] @0 (16KB); 4 KV stages: K[64][64h]+V[64][64h] each 16KB.
// Pair-wise j-block loop: ONE __syncthreads per 2 blocks; Q frags in regs.
// ---------------------------------------------------------------------------
#define FSTG0 16384
#define FSTGSZ 16384
#define FLASH_SMEM (1024 + FSTG0 + 4 * FSTGSZ)   // 83 KB -> 2 CTAs/SM
#define HONES 0x3C003C00u   // half2(1.0, 1.0)

__global__ __launch_bounds__(256) void flash_h_kernel()
{
    extern __shared__ char fsmraw[];
    const uint32_t sb = (smem_u32(fsmraw) + 1023u) & ~1023u;

    const int tid = threadIdx.x;
    const int lane = tid & 31, wid = tid >> 5;
    const int g = lane >> 2, t4 = lane & 3;
    const int bh = blockIdx.y, b = bh >> 4;
    const int qb = (int)(gridDim.x - 1 - blockIdx.x);   // longest first
    const int q0 = qb << 7;
    const size_t base = (size_t)b * CTXT;
    const int ch = (bh & 15) << 6;
    const int rbase = q0 + wid * 16;

    uint32_t paQ, paK[4], paVt[4];
    {
        const int rrA = (lane & 7) + ((lane >> 3) & 1) * 8;
        const int cpA = (lane >> 4) & 1;
        const int r = wid * 16 + rrA;
        paQ = r * 128 + ((cpA ^ (r & 1)) << 4) + (((r >> 1) & 3) << 5);

        const int rrB = (lane & 7) + ((lane >> 4) & 1) * 8;
        const int cpB = (lane >> 3) & 1;
#pragma unroll
        for (int np = 0; np < 4; ++np) {
            int n = np * 16 + rrB;
            paK[np] = n * 128 + ((cpB ^ (n & 1)) << 4) + (((n >> 1) & 3) << 5);
        }
        const int rrV = (lane & 7) + ((lane >> 3) & 1) * 8;   // j within 16
        const int cpV = (lane >> 4) & 1;                      // d chunk within 16
#pragma unroll
        for (int np = 0; np < 4; ++np) {
            int c = 2 * np + cpV;
            paVt[np] = 8192 + rrV * 128 + ((c ^ (rrV & 7)) << 4);
        }
    }

    // Q tile (group 0)
    for (int i = tid; i < 1024; i += 256) {
        const int r = i >> 3, c = i & 7;
        cpa16(sb + r * 128 + ((c ^ (r & 7)) << 4),
              g_Qh + (base + q0 + r) * EMB + ch + c * 8);
    }
    asm volatile("cp.async.commit_group;");

    auto issue_kv = [&](int j0, int st) {
        const uint32_t kb = sb + FSTG0 + st * FSTGSZ;
        for (int i = tid; i < 512; i += 256) {
            const int r = i >> 3, c = i & 7;
            const uint32_t so = r * 128 + ((c ^ (r & 7)) << 4);
            cpa16(kb + so, g_Kh + (base + j0 + r) * EMB + ch + c * 8);
            cpa16(kb + 8192 + so, g_Vh + (base + j0 + r) * EMB + ch + c * 8);
        }
        asm volatile("cp.async.commit_group;");
    };

    const int nblocks = qb * 2 + 2;   // always even
    issue_kv(0, 0);
    issue_kv(64, 1);

    uint32_t qf[4][4];                 // Q fragments, loaded once
    float o[8][4];
    float ol[4] = {0.f, 0.f, 0.f, 0.f};
#pragma unroll
    for (int nt = 0; nt < 8; ++nt)
#pragma unroll
        for (int q = 0; q < 4; ++q) o[nt][q] = 0.f;
    float m0 = -1e30f, m1 = -1e30f;

    for (int jb = 0; jb < nblocks; jb += 2) {
        asm volatile("cp.async.wait_group 0;");
        __syncthreads();
        if (jb == 0) {
#pragma unroll
            for (int s = 0; s < 4; ++s) LDM4(qf[s], (sb + paQ) ^ ((uint32_t)s << 5));
        }
        // prefetch next pair into stages consumed LAST pair (sync above protects)
        if (jb + 2 < nblocks) issue_kv((jb + 2) << 6, (jb + 2) & 3);
        if (jb + 3 < nblocks) issue_kv((jb + 3) << 6, (jb + 3) & 3);

#pragma unroll
        for (int u = 0; u < 2; ++u) {
            const int jbb = jb + u;
            const int j0 = jbb << 6;
            if (j0 > rbase + 15) break;   // fully masked for this warp
            const uint32_t kb = sb + FSTG0 + (jbb & 3) * FSTGSZ;

            // ---- S = Q K^T  (log2 units) ----
            float sc[8][4];
#pragma unroll
            for (int nt = 0; nt < 8; ++nt)
#pragma unroll
                for (int q = 0; q < 4; ++q) sc[nt][q] = 0.f;

#pragma unroll
            for (int s = 0; s < 4; ++s) {
                const uint32_t xs = (uint32_t)s << 5;
                uint32_t bg[4][4];
#pragma unroll
                for (int np = 0; np < 4; ++np) LDM4(bg[np], (kb + paK[np]) ^ xs);
#pragma unroll
                for (int nt = 0; nt < 8; ++nt)
                    MMAH(sc[nt], qf[s], bg[nt >> 1][(nt & 1) * 2],
                         bg[nt >> 1][(nt & 1) * 2 + 1]);
            }

            // ---- causal mask ----
            if (j0 + 63 > rbase) {
                const int r0r = rbase + g, r1r = rbase + g + 8;
#pragma unroll
                for (int nt = 0; nt < 8; ++nt) {
#pragma unroll
                    for (int jj = 0; jj < 2; ++jj) {
                        const int col = j0 + nt * 8 + 2 * t4 + jj;
                        if (col > r0r) sc[nt][jj] = -1e30f;
                        if (col > r1r) sc[nt][2 + jj] = -1e30f;
                    }
                }
            }

            // ---- online softmax (log2 domain) ----
            float mx0 = -1e30f, mx1 = -1e30f;
#pragma unroll
            for (int nt = 0; nt < 8; ++nt) {
                mx0 = fmaxf(mx0, fmaxf(sc[nt][0], sc[nt][1]));
                mx1 = fmaxf(mx1, fmaxf(sc[nt][2], sc[nt][3]));
            }
            mx0 = fmaxf(mx0, __shfl_xor_sync(0xffffffffu, mx0, 1));
            mx0 = fmaxf(mx0, __shfl_xor_sync(0xffffffffu, mx0, 2));
            mx1 = fmaxf(mx1, __shfl_xor_sync(0xffffffffu, mx1, 1));
            mx1 = fmaxf(mx1, __shfl_xor_sync(0xffffffffu, mx1, 2));

            const float mn0 = fmaxf(m0, mx0), mn1 = fmaxf(m1, mx1);
            const float a0 = exp2f(m0 - mn0), a1 = exp2f(m1 - mn1);
            m0 = mn0; m1 = mn1;

#pragma unroll
            for (int nt = 0; nt < 8; ++nt) {
                o[nt][0] *= a0; o[nt][1] *= a0;
                o[nt][2] *= a1; o[nt][3] *= a1;
            }
            ol[0] *= a0; ol[1] *= a0; ol[2] *= a1; ol[3] *= a1;

            // ---- O += P V ; l += P * 1 ----
#pragma unroll
            for (int s = 0; s < 4; ++s) {
                uint32_t ap[4];
                ap[0] = ex2pack(sc[2 * s][0] - mn0, sc[2 * s][1] - mn0);
                ap[1] = ex2pack(sc[2 * s][2] - mn1, sc[2 * s][3] - mn1);
                ap[2] = ex2pack(sc[2 * s + 1][0] - mn0, sc[2 * s + 1][1] - mn0);
                ap[3] = ex2pack(sc[2 * s + 1][2] - mn1, sc[2 * s + 1][3] - mn1);

                MMAH(ol, ap, HONES, HONES);   // row sums

                const uint32_t ro = (uint32_t)s * 2048;
                uint32_t bg[4][4];
#pragma unroll
                for (int np = 0; np < 4; ++np) LDM4T(bg[np], kb + paVt[np] + ro);
#pragma unroll
                for (int nt = 0; nt < 8; ++nt)
                    MMAH(o[nt], ap, bg[nt >> 1][(nt & 1) * 2],
                         bg[nt >> 1][(nt & 1) * 2 + 1]);
            }
        }
    }

    // ---- epilogue: normalize, write AO fp16 ----
    const float inv0 = 1.f / ol[0], inv1 = 1.f / ol[2];
    const size_t r0o = (base + rbase + g) * EMB + ch;
    const size_t r1o = (base + rbase + g + 8) * EMB + ch;
#pragma unroll
    for (int nt = 0; nt < 8; ++nt) {
        const int cc = nt * 8 + 2 * t4;
        *(uint32_t*)(g_ao + r0o + cc) = packh(o[nt][0] * inv0, o[nt][1] * inv0);
        *(uint32_t*)(g_ao + r1o + cc) = packh(o[nt][2] * inv1, o[nt][3] * inv1);
    }
}

// ---------------------------------------------------------------------------
extern "C" void kernel_launch(void* const* d_in, const int* in_sizes, int n_in,
                              void* d_out, int out_size)
{
    (void)in_sizes; (void)n_in; (void)out_size;
    const float* x  = (const float*)d_in[0];
    const float* Wk = (const float*)d_in[1];
    const float* bk = (const float*)d_in[2];
    const float* Wq = (const float*)d_in[3];
    const float* bq = (const float*)d_in[4];
    const float* Wv = (const float*)d_in[5];
    const float* bv = (const float*)d_in[6];
    const float* Wo = (const float*)d_in[7];
    const float* bo = (const float*)d_in[8];

    cudaFuncSetAttribute(flash_h_kernel,
                         cudaFuncAttributeMaxDynamicSharedMemorySize, FLASH_SMEM);
    cudaFuncSetAttribute(gemm_qkv_kernel,
                         cudaFuncAttributeMaxDynamicSharedMemorySize, GEMM_SMEM);
    cudaFuncSetAttribute(gemm_out_kernel,
                         cudaFuncAttributeMaxDynamicSharedMemorySize, GEMM_SMEM);

    conv_x_kernel<<<2048, 256>>>(x);
    conv_wt_kernel<<<dim3(32, 32, 4), 256>>>(Wq, Wk, Wv, Wo);
    gemm_qkv_kernel<<<dim3(8, 32, 3), 256, GEMM_SMEM>>>(bq, bk, bv);
    flash_h_kernel<<<dim3(16, 32), 256, FLASH_SMEM>>>();
    gemm_out_kernel<<<dim3(8, 32), 256, GEMM_SMEM>>>(bo, (float*)d_out);
}